// round 12
// baseline (speedup 1.0000x reference)
#include <cuda_runtime.h>
#include <cuda_fp16.h>
#include <math.h>
#include <stdint.h>

#define B_SZ 4
#define LLEN 4096
#define HDIM 1024
#define PDIM 1024
#define MROWS (B_SZ * LLEN)   /* 16384 */
#define NC 32
#define TCH (LLEN / NC)       /* 128 */

// ---------------- scratch (static device globals; no allocations) ----------
__device__ __half g_bu_re[(size_t)MROWS * PDIM];    // GEMM1 out (fp16), scan in
__device__ __half g_bu_im[(size_t)MROWS * PDIM];
__device__ __half g_u_pack [(size_t)MROWS * HDIM];  // A-fragment-packed fp16
__device__ __half g_xre_pack[(size_t)MROWS * PDIM];
__device__ __half g_xim_pack[(size_t)MROWS * PDIM];
__device__ __half g_Bre_pack[(size_t)PDIM * HDIM];  // B-fragment-packed weights
__device__ __half g_Bim_pack[(size_t)PDIM * HDIM];
__device__ __half g_Cre_pack[(size_t)HDIM * PDIM];
__device__ __half g_Cimn_pack[(size_t)HDIM * PDIM]; // NEGATED C_im
__device__ float g_carry_re[B_SZ * NC * PDIM];
__device__ float g_carry_im[B_SZ * NC * PDIM];
__device__ float g_lam_re[PDIM], g_lam_im[PDIM];
__device__ float g_lamT_re[PDIM], g_lamT_im[PDIM];
__device__ float g_gamma[PDIM];

// ====================== PTX helpers ========================================
__device__ __forceinline__ uint32_t smem_u32(const void* p) {
    uint32_t a;
    asm("{ .reg .u64 t; cvta.to.shared.u64 t, %1; cvt.u32.u64 %0, t; }"
        : "=r"(a) : "l"(p));
    return a;
}
__device__ __forceinline__ void cp16(uint32_t dst, const void* src) {
    asm volatile("cp.async.cg.shared.global [%0], [%1], 16;"
                 :: "r"(dst), "l"(src) : "memory");
}
__device__ __forceinline__ void cp_commit() {
    asm volatile("cp.async.commit_group;" ::: "memory");
}
template <int N>
__device__ __forceinline__ void cp_wait() {
    asm volatile("cp.async.wait_group %0;" :: "n"(N) : "memory");
}
__device__ __forceinline__ uint32_t h2u(__half2 h) { return *(uint32_t*)&h; }
__device__ __forceinline__ void mma_f16(float* d, const uint32_t* a, const uint32_t* b) {
    asm volatile("mma.sync.aligned.m16n8k16.row.col.f32.f16.f16.f32 "
                 "{%0,%1,%2,%3}, {%4,%5,%6,%7}, {%8,%9}, {%0,%1,%2,%3};"
                 : "+f"(d[0]), "+f"(d[1]), "+f"(d[2]), "+f"(d[3])
                 : "r"(a[0]), "r"(a[1]), "r"(a[2]), "r"(a[3]),
                   "r"(b[0]), "r"(b[1]));
}

// ====================== packed fp16 GEMM ===================================
// MODE 0 (GEMM1): BM128 x BN128, 16 chunks; z selects (B0,out0)/(B1,out1);
//                 epi *gamma; fp16 out; 2m x 4n warps
// MODE 1 (GEMM2): BM128 x BN64, 32 chunks, >=16 -> (A1,B1);
//                 epi +Dv[n]*U[m,n]; fp32 out; 4m x 2n warps
#define ASZ 16384                        /* A bytes per stage (both modes) */
#define STG0 32768                       /* MODE0 stage: A16K + B16K */
#define STG1 24576                       /* MODE1 stage: A16K + B8K  */
#define SMEM0 (3 * STG0)                 /* 98304 -> 2 CTAs/SM */
#define SMEM1 (3 * STG1)                 /* 73728 -> 2 CTAs/SM */

template <int MODE>
__global__ __launch_bounds__(256, 2)
void gemm_f16p(const __half* __restrict__ A0, const __half* __restrict__ A1,
               const __half* __restrict__ B0, const __half* __restrict__ B1,
               void* __restrict__ out0, void* __restrict__ out1,
               const float* __restrict__ colscale,
               const float* __restrict__ Dv, const float* __restrict__ U) {
    extern __shared__ char smemc[];
    uint32_t sb = smem_u32(smemc);
    const int tid = threadIdx.x, lane = tid & 31, wid = tid >> 5;
    const int BN_ = (MODE == 0) ? 128 : 64;
    const int NCHUNK = (MODE == 0) ? 16 : 32;
    const int STG = (MODE == 0) ? STG0 : STG1;
    const int brow = blockIdx.y * 128, bcol = blockIdx.x * BN_;

    const char *Ab0, *Ab1, *Bb0, *Bb1;
    void* op;
    if (MODE == 0) {
        Ab0 = Ab1 = (const char*)A0 + (size_t)brow * 2048;
        const __half* Bsel = blockIdx.z ? B1 : B0;
        Bb0 = Bb1 = (const char*)Bsel + (size_t)bcol * 2048;
        op = blockIdx.z ? out1 : out0;
    } else {
        Ab0 = (const char*)A0 + (size_t)brow * 2048;
        Ab1 = (const char*)A1 + (size_t)brow * 2048;
        Bb0 = (const char*)B0 + (size_t)bcol * 2048;
        Bb1 = (const char*)B1 + (size_t)bcol * 2048;
        op = out0;
    }

    // producer gmem bases (chunk-relative)
    // A seg s (0..1023): rb=s>>7, kb=(s>>5)&3, l=s&31 -> (rb*64+kb)*512 + l*16
    // B seg s          : nb=s>>6, kb=(s>>4)&3, q=s&15 -> (nb*64+kb)*256 + q*16
    const int NBSEG = (MODE == 0) ? 4 : 2;   // B segs per thread
    uint32_t agm[4], bgm[4];
#pragma unroll
    for (int j = 0; j < 4; j++) {
        int s = tid + j * 256;
        agm[j] = (uint32_t)((((s >> 7) * 64) + ((s >> 5) & 3)) * 512 + (s & 31) * 16);
    }
#pragma unroll
    for (int j = 0; j < NBSEG; j++) {
        int s = tid + j * 256;
        bgm[j] = (uint32_t)((((s >> 6) * 64) + ((s >> 4) & 3)) * 256 + (s & 15) * 16);
    }
    const uint32_t soff = (uint32_t)tid * 16;

    auto load_chunk = [&](int i) {
        const char* Ap = (MODE == 1 && i >= 16) ? Ab1 : Ab0;
        const char* Bp = (MODE == 1 && i >= 16) ? Bb1 : Bb0;
        uint32_t ka = (uint32_t)(i & 15) * 2048;   // 4 k16 tiles * 512B
        uint32_t kb = (uint32_t)(i & 15) * 1024;   // 4 k16 tiles * 256B
        uint32_t st = sb + (uint32_t)(i % 3) * STG;
#pragma unroll
        for (int j = 0; j < 4; j++)
            cp16(st + soff + j * 4096, Ap + agm[j] + ka);
#pragma unroll
        for (int j = 0; j < NBSEG; j++)
            cp16(st + ASZ + soff + j * 4096, Bp + bgm[j] + kb);
        cp_commit();
    };

    // consumer: MODE0 2m x 4n (warp 64x32), MODE1 4m x 2n (warp 32x32)
    const int NF = (MODE == 0) ? 4 : 2;   // m16 tiles per warp
    const int NJ = 4;                     // n8 tiles per warp (both modes)
    uint32_t afr0, bfr0;
    if (MODE == 0) {
        afr0 = (uint32_t)(((wid >> 2) * 4) * 2048 + lane * 16);
        bfr0 = (uint32_t)(ASZ + ((wid & 3) * 4) * 1024 + lane * 8);
    } else {
        afr0 = (uint32_t)(((wid & 3) * 2) * 2048 + lane * 16);
        bfr0 = (uint32_t)(ASZ + ((wid >> 2) * 4) * 1024 + lane * 8);
    }

    float acc[NF][NJ][4];
#pragma unroll
    for (int f = 0; f < NF; f++)
#pragma unroll
        for (int j = 0; j < NJ; j++)
#pragma unroll
            for (int c = 0; c < 4; c++) acc[f][j][c] = 0.0f;

    load_chunk(0);
    load_chunk(1);

    for (int i = 0; i < NCHUNK; i++) {
        if (i + 2 < NCHUNK) cp_wait<1>();
        else                cp_wait<0>();
        __syncthreads();                       // single sync per chunk
        if (i + 2 < NCHUNK) load_chunk(i + 2); // stage (i+2)%3: free since i-1
        const char* stp = smemc + (i % 3) * STG;
#pragma unroll
        for (int kk = 0; kk < 4; kk++) {
            uint4 a[NF];
            uint2 b[NJ];
#pragma unroll
            for (int f = 0; f < NF; f++)
                a[f] = *(const uint4*)(stp + afr0 + f * 2048 + kk * 512);
#pragma unroll
            for (int j = 0; j < NJ; j++)
                b[j] = *(const uint2*)(stp + bfr0 + j * 1024 + kk * 256);
#pragma unroll
            for (int f = 0; f < NF; f++)
#pragma unroll
                for (int j = 0; j < NJ; j++)
                    mma_f16(acc[f][j], &a[f].x, &b[j].x);
        }
    }

    // ---- epilogue ----
    const int lr = lane >> 2, lc = lane & 3;
    const int wm = (MODE == 0) ? (wid >> 2) * 64 : (wid & 3) * 32;
    const int wn = (MODE == 0) ? (wid & 3) * 32 : (wid >> 2) * 32;
#pragma unroll
    for (int f = 0; f < NF; f++) {
        int r0 = brow + wm + f * 16 + lr;
#pragma unroll
        for (int j = 0; j < NJ; j++) {
            int col = bcol + wn + j * 8 + 2 * lc;
            float d0 = acc[f][j][0], d1 = acc[f][j][1];
            float d2 = acc[f][j][2], d3 = acc[f][j][3];
            if (MODE == 0) {
                float s0 = colscale[col], s1 = colscale[col + 1];
                __half* oph = (__half*)op;
                *(uint32_t*)&oph[(size_t)r0 * 1024 + col] =
                    h2u(__floats2half2_rn(d0 * s0, d1 * s1));
                *(uint32_t*)&oph[(size_t)(r0 + 8) * 1024 + col] =
                    h2u(__floats2half2_rn(d2 * s0, d3 * s1));
            } else {
                float v0 = Dv[col], v1 = Dv[col + 1];
                float2 ua = *(const float2*)&U[(size_t)r0 * HDIM + col];
                float2 ub = *(const float2*)&U[(size_t)(r0 + 8) * HDIM + col];
                float* opf = (float*)op;
                *(float2*)&opf[(size_t)r0 * 1024 + col] =
                    make_float2(d0 + v0 * ua.x, d1 + v1 * ua.y);
                *(float2*)&opf[(size_t)(r0 + 8) * 1024 + col] =
                    make_float2(d2 + v0 * ub.x, d3 + v1 * ub.y);
            }
        }
    }
}

// ====================== pack kernels (fp16 fragments) =======================
__global__ __launch_bounds__(256) void pack_Au(const float* __restrict__ src,
                                               __half* __restrict__ dst) {
    __shared__ float sm[16][260];
    int t = threadIdx.x, rb = blockIdx.x, ks = blockIdx.y;
#pragma unroll
    for (int i = 0; i < 4; i++) {
        int idx = t + i * 256;
        int r = idx >> 6, c = (idx & 63) * 4;
        float4 v = *(const float4*)&src[(size_t)(rb * 16 + r) * 1024 + ks * 256 + c];
        sm[r][c] = v.x; sm[r][c + 1] = v.y; sm[r][c + 2] = v.z; sm[r][c + 3] = v.w;
    }
    __syncthreads();
#pragma unroll
    for (int i = 0; i < 2; i++) {
        int q = t + i * 256;
        int kbl = q >> 5, l = q & 31, g = l >> 2, tt = l & 3;
        int c = kbl * 16 + 2 * tt;
        uint4 o;
        o.x = h2u(__floats2half2_rn(sm[g][c],         sm[g][c + 1]));
        o.y = h2u(__floats2half2_rn(sm[g + 8][c],     sm[g + 8][c + 1]));
        o.z = h2u(__floats2half2_rn(sm[g][c + 8],     sm[g][c + 9]));
        o.w = h2u(__floats2half2_rn(sm[g + 8][c + 8], sm[g + 8][c + 9]));
        ((uint4*)dst)[(size_t)(rb * 64 + ks * 16 + kbl) * 32 + l] = o;
    }
}

__global__ __launch_bounds__(256)
void pack_Bw(const float* __restrict__ s0, __half* __restrict__ d0,
             const float* __restrict__ s1, __half* __restrict__ d1, float sgn1) {
    const float* src = blockIdx.z ? s1 : s0;
    __half* dst = blockIdx.z ? d1 : d0;
    float sg = blockIdx.z ? sgn1 : 1.0f;
    __shared__ float sm[16][260];
    int t = threadIdx.x, rb = blockIdx.x, ks = blockIdx.y;
#pragma unroll
    for (int i = 0; i < 4; i++) {
        int idx = t + i * 256;
        int r = idx >> 6, c = (idx & 63) * 4;
        float4 v = *(const float4*)&src[(size_t)(rb * 16 + r) * 1024 + ks * 256 + c];
        sm[r][c] = sg * v.x; sm[r][c + 1] = sg * v.y;
        sm[r][c + 2] = sg * v.z; sm[r][c + 3] = sg * v.w;
    }
    __syncthreads();
#pragma unroll
    for (int i = 0; i < 4; i++) {
        int u = t + i * 256;
        int nbl = u >> 9, kbl = (u >> 5) & 15, l = u & 31;
        int g = l >> 2, tt = l & 3;
        int row = nbl * 8 + g, c = kbl * 16 + 2 * tt;
        uint2 o;
        o.x = h2u(__floats2half2_rn(sm[row][c],     sm[row][c + 1]));
        o.y = h2u(__floats2half2_rn(sm[row][c + 8], sm[row][c + 9]));
        ((uint2*)dst)[(size_t)((rb * 2 + nbl) * 64 + ks * 16 + kbl) * 32 + l] = o;
    }
}

// ====================== prep / scan ========================================
__global__ void prep_kernel(const float* __restrict__ nu_log,
                            const float* __restrict__ theta_log,
                            const float* __restrict__ gamma_log) {
    int p = blockIdx.x * blockDim.x + threadIdx.x;
    if (p >= PDIM) return;
    float mag = expf(-expf(nu_log[p]));
    float th = expf(theta_log[p]);
    float s, c; sincosf(th, &s, &c);
    float lr = mag * c, li = mag * s;
    g_lam_re[p] = lr; g_lam_im[p] = li;
    g_gamma[p] = expf(gamma_log[p]);
    float ar = lr, ai = li;
#pragma unroll
    for (int i = 0; i < 7; i++) { float nr = ar*ar - ai*ai; ai = 2.0f*ar*ai; ar = nr; }
    g_lamT_re[p] = ar; g_lamT_im[p] = ai;
}

__global__ __launch_bounds__(256) void scan_pass1() {
    int p = blockIdx.x * 256 + threadIdx.x;
    int chunk = blockIdx.y, b = blockIdx.z;
    float lr = g_lam_re[p], li = g_lam_im[p];
    size_t base = ((size_t)(b * LLEN + chunk * TCH)) * PDIM + p;
    float sr = 0.0f, si = 0.0f;
#pragma unroll 4
    for (int t = 0; t < TCH; t++) {
        float br_ = __half2float(g_bu_re[base + (size_t)t * PDIM]);
        float bi_ = __half2float(g_bu_im[base + (size_t)t * PDIM]);
        float nr = fmaf(lr, sr, fmaf(-li, si, br_));
        float ni = fmaf(lr, si, fmaf( li, sr, bi_));
        sr = nr; si = ni;
    }
    int ci = (b * NC + chunk) * PDIM + p;
    g_carry_re[ci] = sr; g_carry_im[ci] = si;
}

__global__ void scan_pass2() {
    int gid = blockIdx.x * blockDim.x + threadIdx.x;
    if (gid >= B_SZ * PDIM) return;
    int b = gid / PDIM, p = gid % PDIM;
    float tr_ = g_lamT_re[p], ti = g_lamT_im[p];
    float cr = 0.0f, ci_ = 0.0f;
    for (int c = 0; c < NC; c++) {
        int idx = (b * NC + c) * PDIM + p;
        float sr = g_carry_re[idx], si = g_carry_im[idx];
        g_carry_re[idx] = cr; g_carry_im[idx] = ci_;
        float nr = fmaf(tr_, cr, fmaf(-ti, ci_, sr));
        float ni = fmaf(tr_, ci_, fmaf( ti, cr, si));
        cr = nr; ci_ = ni;
    }
}

// replay with carry seed; emit A-fragment-packed fp16 x directly
__global__ __launch_bounds__(256) void scan_pass3() {
    __shared__ float smr[16][260];
    __shared__ float smi[16][260];
    int pl = threadIdx.x;
    int p = blockIdx.x * 256 + pl;
    int chunk = blockIdx.y, b = blockIdx.z;
    float lr = g_lam_re[p], li = g_lam_im[p];
    int ci = (b * NC + chunk) * PDIM + p;
    float sr = g_carry_re[ci], si = g_carry_im[ci];
    size_t base = ((size_t)(b * LLEN + chunk * TCH)) * PDIM + p;

    for (int blk = 0; blk < TCH / 16; blk++) {
#pragma unroll 4
        for (int t = 0; t < 16; t++) {
            size_t idx = base + (size_t)(blk * 16 + t) * PDIM;
            float br_ = __half2float(g_bu_re[idx]);
            float bi_ = __half2float(g_bu_im[idx]);
            float nr = fmaf(lr, sr, fmaf(-li, si, br_));
            float ni = fmaf(lr, si, fmaf( li, sr, bi_));
            sr = nr; si = ni;
            smr[t][pl] = sr;
            smi[t][pl] = si;
        }
        __syncthreads();
        size_t rbg = (size_t)(b * LLEN + chunk * TCH + blk * 16) >> 4;
#pragma unroll
        for (int i = 0; i < 2; i++) {
            int q = pl + i * 256;
            int kbl = q >> 5, l = q & 31, g = l >> 2, tt = l & 3;
            int c = kbl * 16 + 2 * tt;
            size_t quad = (rbg * 64 + blockIdx.x * 16 + kbl) * 32 + l;
            uint4 o;
            o.x = h2u(__floats2half2_rn(smr[g][c],         smr[g][c + 1]));
            o.y = h2u(__floats2half2_rn(smr[g + 8][c],     smr[g + 8][c + 1]));
            o.z = h2u(__floats2half2_rn(smr[g][c + 8],     smr[g][c + 9]));
            o.w = h2u(__floats2half2_rn(smr[g + 8][c + 8], smr[g + 8][c + 9]));
            ((uint4*)g_xre_pack)[quad] = o;
            o.x = h2u(__floats2half2_rn(smi[g][c],         smi[g][c + 1]));
            o.y = h2u(__floats2half2_rn(smi[g + 8][c],     smi[g + 8][c + 1]));
            o.z = h2u(__floats2half2_rn(smi[g][c + 8],     smi[g][c + 9]));
            o.w = h2u(__floats2half2_rn(smi[g + 8][c + 8], smi[g + 8][c + 9]));
            ((uint4*)g_xim_pack)[quad] = o;
        }
        __syncthreads();
    }
}

// ====================== launch =============================================
extern "C" void kernel_launch(void* const* d_in, const int* in_sizes, int n_in,
                              void* d_out, int out_size) {
    const float* inputs    = (const float*)d_in[0];
    const float* nu_log    = (const float*)d_in[1];
    const float* theta_log = (const float*)d_in[2];
    const float* B_re      = (const float*)d_in[3];
    const float* B_im      = (const float*)d_in[4];
    const float* C_re      = (const float*)d_in[5];
    const float* C_im      = (const float*)d_in[6];
    const float* Dvec      = (const float*)d_in[7];
    const float* gamma_log = (const float*)d_in[8];
    float* out = (float*)d_out;

    float *gamma_p;
    __half *bu_re, *bu_im, *upack, *xre, *xim, *Bre, *Bim, *Cre, *Cimn;
    cudaGetSymbolAddress((void**)&bu_re, g_bu_re);
    cudaGetSymbolAddress((void**)&bu_im, g_bu_im);
    cudaGetSymbolAddress((void**)&gamma_p, g_gamma);
    cudaGetSymbolAddress((void**)&upack, g_u_pack);
    cudaGetSymbolAddress((void**)&xre, g_xre_pack);
    cudaGetSymbolAddress((void**)&xim, g_xim_pack);
    cudaGetSymbolAddress((void**)&Bre, g_Bre_pack);
    cudaGetSymbolAddress((void**)&Bim, g_Bim_pack);
    cudaGetSymbolAddress((void**)&Cre, g_Cre_pack);
    cudaGetSymbolAddress((void**)&Cimn, g_Cimn_pack);

    cudaFuncSetAttribute(gemm_f16p<0>, cudaFuncAttributeMaxDynamicSharedMemorySize, SMEM0);
    cudaFuncSetAttribute(gemm_f16p<1>, cudaFuncAttributeMaxDynamicSharedMemorySize, SMEM1);

    // launch index:      0      1        2        3(profiled)  4 ...
    prep_kernel<<<4, 256>>>(nu_log, theta_log, gamma_log);
    pack_Au<<<dim3(MROWS / 16, 4), 256>>>(inputs, upack);
    pack_Bw<<<dim3(64, 4, 2), 256>>>(B_re, Bre, B_im, Bim, 1.0f);

    // GEMM1 (launch #3): Bu_{re,im}[m,p] = gamma[p] * sum_h u[m,h] * B_{re,im}[p,h]
    dim3 g1(PDIM / 128, MROWS / 128, 2);
    gemm_f16p<0><<<g1, 256, SMEM0>>>(upack, nullptr, Bre, Bim,
                                     bu_re, bu_im, gamma_p, nullptr, nullptr);

    pack_Bw<<<dim3(64, 4, 2), 256>>>(C_re, Cre, C_im, Cimn, -1.0f);

    // chunked linear recurrence; x emitted packed fp16
    dim3 gs(PDIM / 256, NC, B_SZ);
    scan_pass1<<<gs, 256>>>();
    scan_pass2<<<(B_SZ * PDIM + 255) / 256, 256>>>();
    scan_pass3<<<gs, 256>>>();

    // GEMM2: out = x_re@C_re^T + x_im@(-C_im)^T + D*u  (BN=64, 2048 CTAs)
    dim3 g2(HDIM / 64, MROWS / 128, 1);
    gemm_f16p<1><<<g2, 256, SMEM1>>>(xre, xim, Cre, Cimn,
                                     out, nullptr, nullptr, Dvec, inputs);
}

// round 13
// speedup vs baseline: 1.0733x; 1.0733x over previous
#include <cuda_runtime.h>
#include <cuda_fp16.h>
#include <math.h>
#include <stdint.h>

#define B_SZ 4
#define LLEN 4096
#define HDIM 1024
#define PDIM 1024
#define MROWS (B_SZ * LLEN)   /* 16384 */
#define NC 32
#define TCH (LLEN / NC)       /* 128 */

// ---------------- scratch (static device globals; no allocations) ----------
__device__ __half g_bu_re[(size_t)MROWS * PDIM];    // GEMM1 out (fp16), scan in
__device__ __half g_bu_im[(size_t)MROWS * PDIM];
__device__ __half g_u_pack [(size_t)MROWS * HDIM];  // A-fragment-packed fp16
__device__ __half g_xre_pack[(size_t)MROWS * PDIM];
__device__ __half g_xim_pack[(size_t)MROWS * PDIM];
__device__ __half g_Bre_pack[(size_t)PDIM * HDIM];  // B-fragment-packed weights
__device__ __half g_Bim_pack[(size_t)PDIM * HDIM];
__device__ __half g_Cre_pack[(size_t)HDIM * PDIM];
__device__ __half g_Cimn_pack[(size_t)HDIM * PDIM]; // NEGATED C_im
__device__ float g_carry_re[B_SZ * NC * PDIM];
__device__ float g_carry_im[B_SZ * NC * PDIM];
__device__ float g_lam_re[PDIM], g_lam_im[PDIM];
__device__ float g_lamT_re[PDIM], g_lamT_im[PDIM];
__device__ float g_gamma[PDIM];

// ====================== PTX helpers ========================================
__device__ __forceinline__ uint32_t smem_u32(const void* p) {
    uint32_t a;
    asm("{ .reg .u64 t; cvta.to.shared.u64 t, %1; cvt.u32.u64 %0, t; }"
        : "=r"(a) : "l"(p));
    return a;
}
__device__ __forceinline__ void cp16(uint32_t dst, const void* src) {
    asm volatile("cp.async.cg.shared.global [%0], [%1], 16;"
                 :: "r"(dst), "l"(src) : "memory");
}
__device__ __forceinline__ void cp_commit() {
    asm volatile("cp.async.commit_group;" ::: "memory");
}
template <int N>
__device__ __forceinline__ void cp_wait() {
    asm volatile("cp.async.wait_group %0;" :: "n"(N) : "memory");
}
__device__ __forceinline__ uint32_t h2u(__half2 h) { return *(uint32_t*)&h; }
__device__ __forceinline__ void mma_f16(float* d, const uint32_t* a, const uint32_t* b) {
    asm volatile("mma.sync.aligned.m16n8k16.row.col.f32.f16.f16.f32 "
                 "{%0,%1,%2,%3}, {%4,%5,%6,%7}, {%8,%9}, {%0,%1,%2,%3};"
                 : "+f"(d[0]), "+f"(d[1]), "+f"(d[2]), "+f"(d[3])
                 : "r"(a[0]), "r"(a[1]), "r"(a[2]), "r"(a[3]),
                   "r"(b[0]), "r"(b[1]));
}

// ====================== packed fp16 GEMM (BM128 x BN128) ===================
// MODE 0 (GEMM1): 16 chunks; z selects (B0,out0)/(B1,out1); epi *gamma; fp16 out
// MODE 1 (GEMM2): 32 chunks, >=16 -> (A1,B1); epi +Dv[n]*U[m,n]; fp32 out
#define ASZ 16384                        /* A bytes per stage */
#define STG_BYTES 32768                  /* A 16K + B 16K */
#define SMEM_TOTAL (3 * STG_BYTES)       /* 98304 -> 2 CTAs/SM */

template <int MODE>
__global__ __launch_bounds__(256, 2)
void gemm_f16p(const __half* __restrict__ A0, const __half* __restrict__ A1,
               const __half* __restrict__ B0, const __half* __restrict__ B1,
               void* __restrict__ out0, void* __restrict__ out1,
               const float* __restrict__ colscale,
               const float* __restrict__ Dv, const float* __restrict__ U) {
    extern __shared__ char smemc[];
    uint32_t sb = smem_u32(smemc);
    const int tid = threadIdx.x, lane = tid & 31, wid = tid >> 5;
    const int brow = blockIdx.y * 128, bcol = blockIdx.x * 128;
    const int NCHUNK = (MODE == 0) ? 16 : 32;

    const char *Ab0, *Ab1, *Bb0, *Bb1;
    void* op;
    if (MODE == 0) {
        Ab0 = Ab1 = (const char*)A0 + (size_t)brow * 2048;
        const __half* Bsel = blockIdx.z ? B1 : B0;
        Bb0 = Bb1 = (const char*)Bsel + (size_t)bcol * 2048;
        op = blockIdx.z ? out1 : out0;
    } else {
        Ab0 = (const char*)A0 + (size_t)brow * 2048;
        Ab1 = (const char*)A1 + (size_t)brow * 2048;
        Bb0 = (const char*)B0 + (size_t)bcol * 2048;
        Bb1 = (const char*)B1 + (size_t)bcol * 2048;
        op = out0;
    }

    // producer gmem bases (chunk-relative), 1024 16B segs each
    uint32_t agm[4], bgm[4];
#pragma unroll
    for (int j = 0; j < 4; j++) {
        int s = tid + j * 256;
        agm[j] = (uint32_t)((((s >> 7) * 64) + ((s >> 5) & 3)) * 512 + (s & 31) * 16);
        bgm[j] = (uint32_t)((((s >> 6) * 64) + ((s >> 4) & 3)) * 256 + (s & 15) * 16);
    }
    const uint32_t soff = (uint32_t)tid * 16;

    auto load_chunk = [&](int i) {
        const char* Ap = (MODE == 1 && i >= 16) ? Ab1 : Ab0;
        const char* Bp = (MODE == 1 && i >= 16) ? Bb1 : Bb0;
        uint32_t ka = (uint32_t)(i & 15) * 2048;
        uint32_t kb = (uint32_t)(i & 15) * 1024;
        uint32_t st = sb + (uint32_t)(i % 3) * STG_BYTES;
#pragma unroll
        for (int j = 0; j < 4; j++) {
            cp16(st + soff + j * 4096, Ap + agm[j] + ka);
            cp16(st + ASZ + soff + j * 4096, Bp + bgm[j] + kb);
        }
        cp_commit();
    };

    // consumer: 8 warps as 2m x 4n; warp tile 64x32
    const uint32_t afr0 = (uint32_t)(((wid >> 2) * 4) * 2048 + lane * 16);
    const uint32_t bfr0 = (uint32_t)(ASZ + ((wid & 3) * 4) * 1024 + lane * 8);

    float acc[4][4][4];
#pragma unroll
    for (int f = 0; f < 4; f++)
#pragma unroll
        for (int j = 0; j < 4; j++)
#pragma unroll
            for (int c = 0; c < 4; c++) acc[f][j][c] = 0.0f;

    load_chunk(0);
    load_chunk(1);

    for (int i = 0; i < NCHUNK; i++) {
        if (i + 2 < NCHUNK) cp_wait<1>();
        else                cp_wait<0>();
        __syncthreads();                       // single sync per chunk
        if (i + 2 < NCHUNK) load_chunk(i + 2); // stage (i+2)%3 free since i-1
        const char* stp = smemc + (i % 3) * STG_BYTES;
#pragma unroll
        for (int kk = 0; kk < 4; kk++) {
            uint4 a[4];
            uint2 b[4];
#pragma unroll
            for (int f = 0; f < 4; f++)
                a[f] = *(const uint4*)(stp + afr0 + f * 2048 + kk * 512);
#pragma unroll
            for (int j = 0; j < 4; j++)
                b[j] = *(const uint2*)(stp + bfr0 + j * 1024 + kk * 256);
#pragma unroll
            for (int f = 0; f < 4; f++)
#pragma unroll
                for (int j = 0; j < 4; j++)
                    mma_f16(acc[f][j], &a[f].x, &b[j].x);
        }
    }

    // ---- epilogue ----
    const int lr = lane >> 2, lc = lane & 3;
    const int wm = (wid >> 2) * 64, wn = (wid & 3) * 32;
#pragma unroll
    for (int f = 0; f < 4; f++) {
        int r0 = brow + wm + f * 16 + lr;
#pragma unroll
        for (int j = 0; j < 4; j++) {
            int col = bcol + wn + j * 8 + 2 * lc;
            float d0 = acc[f][j][0], d1 = acc[f][j][1];
            float d2 = acc[f][j][2], d3 = acc[f][j][3];
            if (MODE == 0) {
                float s0 = colscale[col], s1 = colscale[col + 1];
                __half* oph = (__half*)op;
                *(uint32_t*)&oph[(size_t)r0 * 1024 + col] =
                    h2u(__floats2half2_rn(d0 * s0, d1 * s1));
                *(uint32_t*)&oph[(size_t)(r0 + 8) * 1024 + col] =
                    h2u(__floats2half2_rn(d2 * s0, d3 * s1));
            } else {
                float v0 = Dv[col], v1 = Dv[col + 1];
                float2 ua = *(const float2*)&U[(size_t)r0 * HDIM + col];
                float2 ub = *(const float2*)&U[(size_t)(r0 + 8) * HDIM + col];
                float* opf = (float*)op;
                *(float2*)&opf[(size_t)r0 * 1024 + col] =
                    make_float2(d0 + v0 * ua.x, d1 + v1 * ua.y);
                *(float2*)&opf[(size_t)(r0 + 8) * 1024 + col] =
                    make_float2(d2 + v0 * ub.x, d3 + v1 * ub.y);
            }
        }
    }
}

// ====================== pack kernels (fp16 fragments) =======================
__global__ __launch_bounds__(256) void pack_Au(const float* __restrict__ src,
                                               __half* __restrict__ dst) {
    __shared__ float sm[16][260];
    int t = threadIdx.x, rb = blockIdx.x, ks = blockIdx.y;
#pragma unroll
    for (int i = 0; i < 4; i++) {
        int idx = t + i * 256;
        int r = idx >> 6, c = (idx & 63) * 4;
        float4 v = *(const float4*)&src[(size_t)(rb * 16 + r) * 1024 + ks * 256 + c];
        sm[r][c] = v.x; sm[r][c + 1] = v.y; sm[r][c + 2] = v.z; sm[r][c + 3] = v.w;
    }
    __syncthreads();
#pragma unroll
    for (int i = 0; i < 2; i++) {
        int q = t + i * 256;
        int kbl = q >> 5, l = q & 31, g = l >> 2, tt = l & 3;
        int c = kbl * 16 + 2 * tt;
        uint4 o;
        o.x = h2u(__floats2half2_rn(sm[g][c],         sm[g][c + 1]));
        o.y = h2u(__floats2half2_rn(sm[g + 8][c],     sm[g + 8][c + 1]));
        o.z = h2u(__floats2half2_rn(sm[g][c + 8],     sm[g][c + 9]));
        o.w = h2u(__floats2half2_rn(sm[g + 8][c + 8], sm[g + 8][c + 9]));
        ((uint4*)dst)[(size_t)(rb * 64 + ks * 16 + kbl) * 32 + l] = o;
    }
}

__global__ __launch_bounds__(256)
void pack_Bw(const float* __restrict__ s0, __half* __restrict__ d0,
             const float* __restrict__ s1, __half* __restrict__ d1, float sgn1) {
    const float* src = blockIdx.z ? s1 : s0;
    __half* dst = blockIdx.z ? d1 : d0;
    float sg = blockIdx.z ? sgn1 : 1.0f;
    __shared__ float sm[16][260];
    int t = threadIdx.x, rb = blockIdx.x, ks = blockIdx.y;
#pragma unroll
    for (int i = 0; i < 4; i++) {
        int idx = t + i * 256;
        int r = idx >> 6, c = (idx & 63) * 4;
        float4 v = *(const float4*)&src[(size_t)(rb * 16 + r) * 1024 + ks * 256 + c];
        sm[r][c] = sg * v.x; sm[r][c + 1] = sg * v.y;
        sm[r][c + 2] = sg * v.z; sm[r][c + 3] = sg * v.w;
    }
    __syncthreads();
#pragma unroll
    for (int i = 0; i < 4; i++) {
        int u = t + i * 256;
        int nbl = u >> 9, kbl = (u >> 5) & 15, l = u & 31;
        int g = l >> 2, tt = l & 3;
        int row = nbl * 8 + g, c = kbl * 16 + 2 * tt;
        uint2 o;
        o.x = h2u(__floats2half2_rn(sm[row][c],     sm[row][c + 1]));
        o.y = h2u(__floats2half2_rn(sm[row][c + 8], sm[row][c + 9]));
        ((uint2*)dst)[(size_t)((rb * 2 + nbl) * 64 + ks * 16 + kbl) * 32 + l] = o;
    }
}

// ====================== prep / scan ========================================
__global__ void prep_kernel(const float* __restrict__ nu_log,
                            const float* __restrict__ theta_log,
                            const float* __restrict__ gamma_log) {
    int p = blockIdx.x * blockDim.x + threadIdx.x;
    if (p >= PDIM) return;
    float mag = expf(-expf(nu_log[p]));
    float th = expf(theta_log[p]);
    float s, c; sincosf(th, &s, &c);
    float lr = mag * c, li = mag * s;
    g_lam_re[p] = lr; g_lam_im[p] = li;
    g_gamma[p] = expf(gamma_log[p]);
    float ar = lr, ai = li;
#pragma unroll
    for (int i = 0; i < 7; i++) { float nr = ar*ar - ai*ai; ai = 2.0f*ar*ai; ar = nr; }
    g_lamT_re[p] = ar; g_lamT_im[p] = ai;
}

__global__ __launch_bounds__(256) void scan_pass1() {
    int p = blockIdx.x * 256 + threadIdx.x;
    int chunk = blockIdx.y, b = blockIdx.z;
    float lr = g_lam_re[p], li = g_lam_im[p];
    size_t base = ((size_t)(b * LLEN + chunk * TCH)) * PDIM + p;
    float sr = 0.0f, si = 0.0f;
#pragma unroll 4
    for (int t = 0; t < TCH; t++) {
        float br_ = __half2float(g_bu_re[base + (size_t)t * PDIM]);
        float bi_ = __half2float(g_bu_im[base + (size_t)t * PDIM]);
        float nr = fmaf(lr, sr, fmaf(-li, si, br_));
        float ni = fmaf(lr, si, fmaf( li, sr, bi_));
        sr = nr; si = ni;
    }
    int ci = (b * NC + chunk) * PDIM + p;
    g_carry_re[ci] = sr; g_carry_im[ci] = si;
}

__global__ void scan_pass2() {
    int gid = blockIdx.x * blockDim.x + threadIdx.x;
    if (gid >= B_SZ * PDIM) return;
    int b = gid / PDIM, p = gid % PDIM;
    float tr_ = g_lamT_re[p], ti = g_lamT_im[p];
    float cr = 0.0f, ci_ = 0.0f;
    for (int c = 0; c < NC; c++) {
        int idx = (b * NC + c) * PDIM + p;
        float sr = g_carry_re[idx], si = g_carry_im[idx];
        g_carry_re[idx] = cr; g_carry_im[idx] = ci_;
        float nr = fmaf(tr_, cr, fmaf(-ti, ci_, sr));
        float ni = fmaf(tr_, ci_, fmaf( ti, cr, si));
        cr = nr; ci_ = ni;
    }
}

// replay with carry seed; emit A-fragment-packed fp16 x directly
__global__ __launch_bounds__(256) void scan_pass3() {
    __shared__ float smr[16][260];
    __shared__ float smi[16][260];
    int pl = threadIdx.x;
    int p = blockIdx.x * 256 + pl;
    int chunk = blockIdx.y, b = blockIdx.z;
    float lr = g_lam_re[p], li = g_lam_im[p];
    int ci = (b * NC + chunk) * PDIM + p;
    float sr = g_carry_re[ci], si = g_carry_im[ci];
    size_t base = ((size_t)(b * LLEN + chunk * TCH)) * PDIM + p;

    for (int blk = 0; blk < TCH / 16; blk++) {
#pragma unroll 4
        for (int t = 0; t < 16; t++) {
            size_t idx = base + (size_t)(blk * 16 + t) * PDIM;
            float br_ = __half2float(g_bu_re[idx]);
            float bi_ = __half2float(g_bu_im[idx]);
            float nr = fmaf(lr, sr, fmaf(-li, si, br_));
            float ni = fmaf(lr, si, fmaf( li, sr, bi_));
            sr = nr; si = ni;
            smr[t][pl] = sr;
            smi[t][pl] = si;
        }
        __syncthreads();
        size_t rbg = (size_t)(b * LLEN + chunk * TCH + blk * 16) >> 4;
#pragma unroll
        for (int i = 0; i < 2; i++) {
            int q = pl + i * 256;
            int kbl = q >> 5, l = q & 31, g = l >> 2, tt = l & 3;
            int c = kbl * 16 + 2 * tt;
            size_t quad = (rbg * 64 + blockIdx.x * 16 + kbl) * 32 + l;
            uint4 o;
            o.x = h2u(__floats2half2_rn(smr[g][c],         smr[g][c + 1]));
            o.y = h2u(__floats2half2_rn(smr[g + 8][c],     smr[g + 8][c + 1]));
            o.z = h2u(__floats2half2_rn(smr[g][c + 8],     smr[g][c + 9]));
            o.w = h2u(__floats2half2_rn(smr[g + 8][c + 8], smr[g + 8][c + 9]));
            ((uint4*)g_xre_pack)[quad] = o;
            o.x = h2u(__floats2half2_rn(smi[g][c],         smi[g][c + 1]));
            o.y = h2u(__floats2half2_rn(smi[g + 8][c],     smi[g + 8][c + 1]));
            o.z = h2u(__floats2half2_rn(smi[g][c + 8],     smi[g][c + 9]));
            o.w = h2u(__floats2half2_rn(smi[g + 8][c + 8], smi[g + 8][c + 9]));
            ((uint4*)g_xim_pack)[quad] = o;
        }
        __syncthreads();
    }
}

// ====================== launch =============================================
extern "C" void kernel_launch(void* const* d_in, const int* in_sizes, int n_in,
                              void* d_out, int out_size) {
    const float* inputs    = (const float*)d_in[0];
    const float* nu_log    = (const float*)d_in[1];
    const float* theta_log = (const float*)d_in[2];
    const float* B_re      = (const float*)d_in[3];
    const float* B_im      = (const float*)d_in[4];
    const float* C_re      = (const float*)d_in[5];
    const float* C_im      = (const float*)d_in[6];
    const float* Dvec      = (const float*)d_in[7];
    const float* gamma_log = (const float*)d_in[8];
    float* out = (float*)d_out;

    float *gamma_p;
    __half *bu_re, *bu_im, *upack, *xre, *xim, *Bre, *Bim, *Cre, *Cimn;
    cudaGetSymbolAddress((void**)&bu_re, g_bu_re);
    cudaGetSymbolAddress((void**)&bu_im, g_bu_im);
    cudaGetSymbolAddress((void**)&gamma_p, g_gamma);
    cudaGetSymbolAddress((void**)&upack, g_u_pack);
    cudaGetSymbolAddress((void**)&xre, g_xre_pack);
    cudaGetSymbolAddress((void**)&xim, g_xim_pack);
    cudaGetSymbolAddress((void**)&Bre, g_Bre_pack);
    cudaGetSymbolAddress((void**)&Bim, g_Bim_pack);
    cudaGetSymbolAddress((void**)&Cre, g_Cre_pack);
    cudaGetSymbolAddress((void**)&Cimn, g_Cimn_pack);

    cudaFuncSetAttribute(gemm_f16p<0>, cudaFuncAttributeMaxDynamicSharedMemorySize, SMEM_TOTAL);
    cudaFuncSetAttribute(gemm_f16p<1>, cudaFuncAttributeMaxDynamicSharedMemorySize, SMEM_TOTAL);

    // launch index:      0      1        2        3(profiled)  4 ...
    prep_kernel<<<4, 256>>>(nu_log, theta_log, gamma_log);
    pack_Au<<<dim3(MROWS / 16, 4), 256>>>(inputs, upack);
    pack_Bw<<<dim3(64, 4, 2), 256>>>(B_re, Bre, B_im, Bim, 1.0f);

    // GEMM1 (launch #3): Bu_{re,im}[m,p] = gamma[p] * sum_h u[m,h] * B_{re,im}[p,h]
    dim3 g1(PDIM / 128, MROWS / 128, 2);
    gemm_f16p<0><<<g1, 256, SMEM_TOTAL>>>(upack, nullptr, Bre, Bim,
                                          bu_re, bu_im, gamma_p, nullptr, nullptr);

    pack_Bw<<<dim3(64, 4, 2), 256>>>(C_re, Cre, C_im, Cimn, -1.0f);

    // chunked linear recurrence; x emitted packed fp16
    dim3 gs(PDIM / 256, NC, B_SZ);
    scan_pass1<<<gs, 256>>>();
    scan_pass2<<<(B_SZ * PDIM + 255) / 256, 256>>>();
    scan_pass3<<<gs, 256>>>();

    // GEMM2: out = x_re@C_re^T + x_im@(-C_im)^T + D*u
    dim3 g2(HDIM / 128, MROWS / 128, 1);
    gemm_f16p<1><<<g2, 256, SMEM_TOTAL>>>(xre, xim, Cre, Cimn,
                                          out, nullptr, nullptr, Dvec, inputs);
}

// round 14
// speedup vs baseline: 1.0994x; 1.0243x over previous
#include <cuda_runtime.h>
#include <cuda_fp16.h>
#include <math.h>
#include <stdint.h>

#define B_SZ 4
#define LLEN 4096
#define HDIM 1024
#define PDIM 1024
#define MROWS (B_SZ * LLEN)   /* 16384 */
#define NC 32
#define TCH (LLEN / NC)       /* 128 */

// ---------------- scratch (static device globals; no allocations) ----------
__device__ __half g_bu_re[(size_t)MROWS * PDIM];    // GEMM1 out (fp16), scan in
__device__ __half g_bu_im[(size_t)MROWS * PDIM];
__device__ __half g_u_pack [(size_t)MROWS * HDIM];  // A-fragment-packed fp16
__device__ __half g_xre_pack[(size_t)MROWS * PDIM];
__device__ __half g_xim_pack[(size_t)MROWS * PDIM];
__device__ __half g_Bre_pack[(size_t)PDIM * HDIM];  // B-fragment-packed weights
__device__ __half g_Bim_pack[(size_t)PDIM * HDIM];
__device__ __half g_Cre_pack[(size_t)HDIM * PDIM];
__device__ __half g_Cimn_pack[(size_t)HDIM * PDIM]; // NEGATED C_im
__device__ float g_carry_re[B_SZ * NC * PDIM];
__device__ float g_carry_im[B_SZ * NC * PDIM];
__device__ float g_lam_re[PDIM], g_lam_im[PDIM];
__device__ float g_lamT_re[PDIM], g_lamT_im[PDIM];
__device__ float g_gamma[PDIM];

// ====================== PTX helpers ========================================
__device__ __forceinline__ uint32_t smem_u32(const void* p) {
    uint32_t a;
    asm("{ .reg .u64 t; cvta.to.shared.u64 t, %1; cvt.u32.u64 %0, t; }"
        : "=r"(a) : "l"(p));
    return a;
}
__device__ __forceinline__ void cp16(uint32_t dst, const void* src) {
    asm volatile("cp.async.cg.shared.global [%0], [%1], 16;"
                 :: "r"(dst), "l"(src) : "memory");
}
__device__ __forceinline__ void cp_commit() {
    asm volatile("cp.async.commit_group;" ::: "memory");
}
template <int N>
__device__ __forceinline__ void cp_wait() {
    asm volatile("cp.async.wait_group %0;" :: "n"(N) : "memory");
}
__device__ __forceinline__ uint32_t h2u(__half2 h) { return *(uint32_t*)&h; }
__device__ __forceinline__ void mma_f16(float* d, const uint32_t* a, const uint32_t* b) {
    asm volatile("mma.sync.aligned.m16n8k16.row.col.f32.f16.f16.f32 "
                 "{%0,%1,%2,%3}, {%4,%5,%6,%7}, {%8,%9}, {%0,%1,%2,%3};"
                 : "+f"(d[0]), "+f"(d[1]), "+f"(d[2]), "+f"(d[3])
                 : "r"(a[0]), "r"(a[1]), "r"(a[2]), "r"(a[3]),
                   "r"(b[0]), "r"(b[1]));
}

// ====================== packed fp16 GEMM (BM128 x BN128) ===================
// MODE 0 (GEMM1): 16 chunks; z selects (B0,out0)/(B1,out1); epi *gamma; fp16 out
// MODE 1 (GEMM2): 32 chunks, >=16 -> (A1,B1); epi +Dv[n]*u (fp16 packed); fp32 out
#define ASZ 16384                        /* A bytes per stage */
#define STG_BYTES 32768                  /* A 16K + B 16K */
#define SMEM_TOTAL (3 * STG_BYTES)       /* 98304 -> 2 CTAs/SM */

template <int MODE>
__global__ __launch_bounds__(256, 2)
void gemm_f16p(const __half* __restrict__ A0, const __half* __restrict__ A1,
               const __half* __restrict__ B0, const __half* __restrict__ B1,
               void* __restrict__ out0, void* __restrict__ out1,
               const float* __restrict__ colscale,
               const float* __restrict__ Dv, const __half* __restrict__ Upk) {
    extern __shared__ char smemc[];
    uint32_t sb = smem_u32(smemc);
    const int tid = threadIdx.x, lane = tid & 31, wid = tid >> 5;
    const int brow = blockIdx.y * 128, bcol = blockIdx.x * 128;
    const int NCHUNK = (MODE == 0) ? 16 : 32;

    const char *Ab0, *Ab1, *Bb0, *Bb1;
    void* op;
    if (MODE == 0) {
        Ab0 = Ab1 = (const char*)A0 + (size_t)brow * 2048;
        const __half* Bsel = blockIdx.z ? B1 : B0;
        Bb0 = Bb1 = (const char*)Bsel + (size_t)bcol * 2048;
        op = blockIdx.z ? out1 : out0;
    } else {
        Ab0 = (const char*)A0 + (size_t)brow * 2048;
        Ab1 = (const char*)A1 + (size_t)brow * 2048;
        Bb0 = (const char*)B0 + (size_t)bcol * 2048;
        Bb1 = (const char*)B1 + (size_t)bcol * 2048;
        op = out0;
    }

    // producer gmem bases (chunk-relative), 1024 16B segs each
    uint32_t agm[4], bgm[4];
#pragma unroll
    for (int j = 0; j < 4; j++) {
        int s = tid + j * 256;
        agm[j] = (uint32_t)((((s >> 7) * 64) + ((s >> 5) & 3)) * 512 + (s & 31) * 16);
        bgm[j] = (uint32_t)((((s >> 6) * 64) + ((s >> 4) & 3)) * 256 + (s & 15) * 16);
    }
    const uint32_t soff = (uint32_t)tid * 16;

    auto load_chunk = [&](int i) {
        const char* Ap = (MODE == 1 && i >= 16) ? Ab1 : Ab0;
        const char* Bp = (MODE == 1 && i >= 16) ? Bb1 : Bb0;
        uint32_t ka = (uint32_t)(i & 15) * 2048;
        uint32_t kb = (uint32_t)(i & 15) * 1024;
        uint32_t st = sb + (uint32_t)(i % 3) * STG_BYTES;
#pragma unroll
        for (int j = 0; j < 4; j++) {
            cp16(st + soff + j * 4096, Ap + agm[j] + ka);
            cp16(st + ASZ + soff + j * 4096, Bp + bgm[j] + kb);
        }
        cp_commit();
    };

    // consumer: 8 warps as 2m x 4n; warp tile 64x32
    const uint32_t afr0 = (uint32_t)(((wid >> 2) * 4) * 2048 + lane * 16);
    const uint32_t bfr0 = (uint32_t)(ASZ + ((wid & 3) * 4) * 1024 + lane * 8);

    float acc[4][4][4];
#pragma unroll
    for (int f = 0; f < 4; f++)
#pragma unroll
        for (int j = 0; j < 4; j++)
#pragma unroll
            for (int c = 0; c < 4; c++) acc[f][j][c] = 0.0f;

    load_chunk(0);
    load_chunk(1);

    for (int i = 0; i < NCHUNK; i++) {
        if (i + 2 < NCHUNK) cp_wait<1>();
        else                cp_wait<0>();
        __syncthreads();                       // single sync per chunk
        if (i + 2 < NCHUNK) load_chunk(i + 2); // stage (i+2)%3 free since i-1
        const char* stp = smemc + (i % 3) * STG_BYTES;
#pragma unroll
        for (int kk = 0; kk < 4; kk++) {
            uint4 a[4];
            uint2 b[4];
#pragma unroll
            for (int f = 0; f < 4; f++)
                a[f] = *(const uint4*)(stp + afr0 + f * 2048 + kk * 512);
#pragma unroll
            for (int j = 0; j < 4; j++)
                b[j] = *(const uint2*)(stp + bfr0 + j * 1024 + kk * 256);
#pragma unroll
            for (int f = 0; f < 4; f++)
#pragma unroll
                for (int j = 0; j < 4; j++)
                    mma_f16(acc[f][j], &a[f].x, &b[j].x);
        }
    }

    // ---- epilogue ----
    const int lr = lane >> 2, lc = lane & 3;
    const int wm = (wid >> 2) * 64, wn = (wid & 3) * 32;
#pragma unroll
    for (int f = 0; f < 4; f++) {
        int r0 = brow + wm + f * 16 + lr;
#pragma unroll
        for (int j = 0; j < 4; j++) {
            int col = bcol + wn + j * 8 + 2 * lc;
            float d0 = acc[f][j][0], d1 = acc[f][j][1];
            float d2 = acc[f][j][2], d3 = acc[f][j][3];
            if (MODE == 0) {
                float s0 = colscale[col], s1 = colscale[col + 1];
                __half* oph = (__half*)op;
                *(uint32_t*)&oph[(size_t)r0 * 1024 + col] =
                    h2u(__floats2half2_rn(d0 * s0, d1 * s1));
                *(uint32_t*)&oph[(size_t)(r0 + 8) * 1024 + col] =
                    h2u(__floats2half2_rn(d2 * s0, d3 * s1));
            } else {
                // u from A-fragment-packed fp16: quad (r0>>4, col>>4), lane l
                float v0 = Dv[col], v1 = Dv[col + 1];
                size_t quad = ((size_t)(r0 >> 4) * 64 + (col >> 4)) * 32 + lane;
                uint2 uv = *(const uint2*)((const char*)Upk + quad * 16 + (j & 1) * 8);
                __half2 ulo = *(__half2*)&uv.x;   // u(r0,col), u(r0,col+1)
                __half2 uhi = *(__half2*)&uv.y;   // u(r0+8,col), u(r0+8,col+1)
                d0 += v0 * __half2float(ulo.x); d1 += v1 * __half2float(ulo.y);
                d2 += v0 * __half2float(uhi.x); d3 += v1 * __half2float(uhi.y);
                float* opf = (float*)op;
                *(float2*)&opf[(size_t)r0 * 1024 + col] = make_float2(d0, d1);
                *(float2*)&opf[(size_t)(r0 + 8) * 1024 + col] = make_float2(d2, d3);
            }
        }
    }
}

// ====================== fused prep + weight packs ==========================
// blocks [0,512):   pack B_re/B_im -> Bre/Bim (sgn +1)
// blocks [512,1024): pack C_re/C_im -> Cre/Cimn (sgn -1 on im)
// blocks [1024,1028): lambda/gamma prep
__device__ __forceinline__ void pack_bw_body(
    float sm[16][260], int idx,
    const float* __restrict__ s0, __half* __restrict__ d0,
    const float* __restrict__ s1, __half* __restrict__ d1, float sgn1) {
    int z = idx >> 8, rem = idx & 255;
    int rb = rem >> 2, ks = rem & 3;
    const float* src = z ? s1 : s0;
    __half* dst = z ? d1 : d0;
    float sg = z ? sgn1 : 1.0f;
    int t = threadIdx.x;
#pragma unroll
    for (int i = 0; i < 4; i++) {
        int id = t + i * 256;
        int r = id >> 6, c = (id & 63) * 4;
        float4 v = *(const float4*)&src[(size_t)(rb * 16 + r) * 1024 + ks * 256 + c];
        sm[r][c] = sg * v.x; sm[r][c + 1] = sg * v.y;
        sm[r][c + 2] = sg * v.z; sm[r][c + 3] = sg * v.w;
    }
    __syncthreads();
#pragma unroll
    for (int i = 0; i < 4; i++) {
        int u = t + i * 256;
        int nbl = u >> 9, kbl = (u >> 5) & 15, l = u & 31;
        int g = l >> 2, tt = l & 3;
        int row = nbl * 8 + g, c = kbl * 16 + 2 * tt;
        uint2 o;
        o.x = h2u(__floats2half2_rn(sm[row][c],     sm[row][c + 1]));
        o.y = h2u(__floats2half2_rn(sm[row][c + 8], sm[row][c + 9]));
        ((uint2*)dst)[(size_t)((rb * 2 + nbl) * 64 + ks * 16 + kbl) * 32 + l] = o;
    }
}

__global__ __launch_bounds__(256)
void prep_weights(const float* __restrict__ nu_log,
                  const float* __restrict__ theta_log,
                  const float* __restrict__ gamma_log,
                  const float* __restrict__ B_re, __half* __restrict__ Bre,
                  const float* __restrict__ B_im, __half* __restrict__ Bim,
                  const float* __restrict__ C_re, __half* __restrict__ Cre,
                  const float* __restrict__ C_im, __half* __restrict__ Cimn) {
    __shared__ float sm[16][260];
    int bid = blockIdx.x;
    if (bid < 512) {
        pack_bw_body(sm, bid, B_re, Bre, B_im, Bim, 1.0f);
    } else if (bid < 1024) {
        pack_bw_body(sm, bid - 512, C_re, Cre, C_im, Cimn, -1.0f);
    } else {
        int p = (bid - 1024) * 256 + threadIdx.x;
        if (p < PDIM) {
            float mag = expf(-expf(nu_log[p]));
            float th = expf(theta_log[p]);
            float s, c; sincosf(th, &s, &c);
            float lr = mag * c, li = mag * s;
            g_lam_re[p] = lr; g_lam_im[p] = li;
            g_gamma[p] = expf(gamma_log[p]);
            float ar = lr, ai = li;
#pragma unroll
            for (int i = 0; i < 7; i++) { float nr = ar*ar - ai*ai; ai = 2.0f*ar*ai; ar = nr; }
            g_lamT_re[p] = ar; g_lamT_im[p] = ai;
        }
    }
}

// ====================== pack_Au ============================================
__global__ __launch_bounds__(256) void pack_Au(const float* __restrict__ src,
                                               __half* __restrict__ dst) {
    __shared__ float sm[16][260];
    int t = threadIdx.x, rb = blockIdx.x, ks = blockIdx.y;
#pragma unroll
    for (int i = 0; i < 4; i++) {
        int idx = t + i * 256;
        int r = idx >> 6, c = (idx & 63) * 4;
        float4 v = *(const float4*)&src[(size_t)(rb * 16 + r) * 1024 + ks * 256 + c];
        sm[r][c] = v.x; sm[r][c + 1] = v.y; sm[r][c + 2] = v.z; sm[r][c + 3] = v.w;
    }
    __syncthreads();
#pragma unroll
    for (int i = 0; i < 2; i++) {
        int q = t + i * 256;
        int kbl = q >> 5, l = q & 31, g = l >> 2, tt = l & 3;
        int c = kbl * 16 + 2 * tt;
        uint4 o;
        o.x = h2u(__floats2half2_rn(sm[g][c],         sm[g][c + 1]));
        o.y = h2u(__floats2half2_rn(sm[g + 8][c],     sm[g + 8][c + 1]));
        o.z = h2u(__floats2half2_rn(sm[g][c + 8],     sm[g][c + 9]));
        o.w = h2u(__floats2half2_rn(sm[g + 8][c + 8], sm[g + 8][c + 9]));
        ((uint4*)dst)[(size_t)(rb * 64 + ks * 16 + kbl) * 32 + l] = o;
    }
}

// ====================== scan ================================================
__global__ __launch_bounds__(256) void scan_pass1() {
    int p = blockIdx.x * 256 + threadIdx.x;
    int chunk = blockIdx.y, b = blockIdx.z;
    float lr = g_lam_re[p], li = g_lam_im[p];
    size_t base = ((size_t)(b * LLEN + chunk * TCH)) * PDIM + p;
    float sr = 0.0f, si = 0.0f;
#pragma unroll 4
    for (int t = 0; t < TCH; t++) {
        float br_ = __half2float(g_bu_re[base + (size_t)t * PDIM]);
        float bi_ = __half2float(g_bu_im[base + (size_t)t * PDIM]);
        float nr = fmaf(lr, sr, fmaf(-li, si, br_));
        float ni = fmaf(lr, si, fmaf( li, sr, bi_));
        sr = nr; si = ni;
    }
    int ci = (b * NC + chunk) * PDIM + p;
    g_carry_re[ci] = sr; g_carry_im[ci] = si;
}

__global__ void scan_pass2() {
    int gid = blockIdx.x * blockDim.x + threadIdx.x;
    if (gid >= B_SZ * PDIM) return;
    int b = gid / PDIM, p = gid % PDIM;
    float tr_ = g_lamT_re[p], ti = g_lamT_im[p];
    float cr = 0.0f, ci_ = 0.0f;
    for (int c = 0; c < NC; c++) {
        int idx = (b * NC + c) * PDIM + p;
        float sr = g_carry_re[idx], si = g_carry_im[idx];
        g_carry_re[idx] = cr; g_carry_im[idx] = ci_;
        float nr = fmaf(tr_, cr, fmaf(-ti, ci_, sr));
        float ni = fmaf(tr_, ci_, fmaf( ti, cr, si));
        cr = nr; ci_ = ni;
    }
}

// replay with carry seed; emit A-fragment-packed fp16 x directly
__global__ __launch_bounds__(256) void scan_pass3() {
    __shared__ float smr[16][260];
    __shared__ float smi[16][260];
    int pl = threadIdx.x;
    int p = blockIdx.x * 256 + pl;
    int chunk = blockIdx.y, b = blockIdx.z;
    float lr = g_lam_re[p], li = g_lam_im[p];
    int ci = (b * NC + chunk) * PDIM + p;
    float sr = g_carry_re[ci], si = g_carry_im[ci];
    size_t base = ((size_t)(b * LLEN + chunk * TCH)) * PDIM + p;

    for (int blk = 0; blk < TCH / 16; blk++) {
#pragma unroll 4
        for (int t = 0; t < 16; t++) {
            size_t idx = base + (size_t)(blk * 16 + t) * PDIM;
            float br_ = __half2float(g_bu_re[idx]);
            float bi_ = __half2float(g_bu_im[idx]);
            float nr = fmaf(lr, sr, fmaf(-li, si, br_));
            float ni = fmaf(lr, si, fmaf( li, sr, bi_));
            sr = nr; si = ni;
            smr[t][pl] = sr;
            smi[t][pl] = si;
        }
        __syncthreads();
        size_t rbg = (size_t)(b * LLEN + chunk * TCH + blk * 16) >> 4;
#pragma unroll
        for (int i = 0; i < 2; i++) {
            int q = pl + i * 256;
            int kbl = q >> 5, l = q & 31, g = l >> 2, tt = l & 3;
            int c = kbl * 16 + 2 * tt;
            size_t quad = (rbg * 64 + blockIdx.x * 16 + kbl) * 32 + l;
            uint4 o;
            o.x = h2u(__floats2half2_rn(smr[g][c],         smr[g][c + 1]));
            o.y = h2u(__floats2half2_rn(smr[g + 8][c],     smr[g + 8][c + 1]));
            o.z = h2u(__floats2half2_rn(smr[g][c + 8],     smr[g][c + 9]));
            o.w = h2u(__floats2half2_rn(smr[g + 8][c + 8], smr[g + 8][c + 9]));
            ((uint4*)g_xre_pack)[quad] = o;
            o.x = h2u(__floats2half2_rn(smi[g][c],         smi[g][c + 1]));
            o.y = h2u(__floats2half2_rn(smi[g + 8][c],     smi[g + 8][c + 1]));
            o.z = h2u(__floats2half2_rn(smi[g][c + 8],     smi[g][c + 9]));
            o.w = h2u(__floats2half2_rn(smi[g + 8][c + 8], smi[g + 8][c + 9]));
            ((uint4*)g_xim_pack)[quad] = o;
        }
        __syncthreads();
    }
}

// ====================== launch =============================================
extern "C" void kernel_launch(void* const* d_in, const int* in_sizes, int n_in,
                              void* d_out, int out_size) {
    const float* inputs    = (const float*)d_in[0];
    const float* nu_log    = (const float*)d_in[1];
    const float* theta_log = (const float*)d_in[2];
    const float* B_re      = (const float*)d_in[3];
    const float* B_im      = (const float*)d_in[4];
    const float* C_re      = (const float*)d_in[5];
    const float* C_im      = (const float*)d_in[6];
    const float* Dvec      = (const float*)d_in[7];
    const float* gamma_log = (const float*)d_in[8];
    float* out = (float*)d_out;

    float *gamma_p;
    __half *bu_re, *bu_im, *upack, *xre, *xim, *Bre, *Bim, *Cre, *Cimn;
    cudaGetSymbolAddress((void**)&bu_re, g_bu_re);
    cudaGetSymbolAddress((void**)&bu_im, g_bu_im);
    cudaGetSymbolAddress((void**)&gamma_p, g_gamma);
    cudaGetSymbolAddress((void**)&upack, g_u_pack);
    cudaGetSymbolAddress((void**)&xre, g_xre_pack);
    cudaGetSymbolAddress((void**)&xim, g_xim_pack);
    cudaGetSymbolAddress((void**)&Bre, g_Bre_pack);
    cudaGetSymbolAddress((void**)&Bim, g_Bim_pack);
    cudaGetSymbolAddress((void**)&Cre, g_Cre_pack);
    cudaGetSymbolAddress((void**)&Cimn, g_Cimn_pack);

    cudaFuncSetAttribute(gemm_f16p<0>, cudaFuncAttributeMaxDynamicSharedMemorySize, SMEM_TOTAL);
    cudaFuncSetAttribute(gemm_f16p<1>, cudaFuncAttributeMaxDynamicSharedMemorySize, SMEM_TOTAL);

    // launches: 0 prep_weights, 1 pack_Au, 2 GEMM1, 3 scan1(profiled),
    //           4 scan2, 5 scan3, 6 GEMM2
    prep_weights<<<1028, 256>>>(nu_log, theta_log, gamma_log,
                                B_re, Bre, B_im, Bim, C_re, Cre, C_im, Cimn);
    pack_Au<<<dim3(MROWS / 16, 4), 256>>>(inputs, upack);

    // GEMM1: Bu_{re,im}[m,p] = gamma[p] * sum_h u[m,h] * B_{re,im}[p,h]
    dim3 g1(PDIM / 128, MROWS / 128, 2);
    gemm_f16p<0><<<g1, 256, SMEM_TOTAL>>>(upack, nullptr, Bre, Bim,
                                          bu_re, bu_im, gamma_p, nullptr, nullptr);

    // chunked linear recurrence; x emitted packed fp16
    dim3 gs(PDIM / 256, NC, B_SZ);
    scan_pass1<<<gs, 256>>>();
    scan_pass2<<<(B_SZ * PDIM + 255) / 256, 256>>>();
    scan_pass3<<<gs, 256>>>();

    // GEMM2: out = x_re@C_re^T + x_im@(-C_im)^T + D*u (u from fp16 pack)
    dim3 g2(HDIM / 128, MROWS / 128, 1);
    gemm_f16p<1><<<g2, 256, SMEM_TOTAL>>>(xre, xim, Cre, Cimn,
                                          out, nullptr, nullptr, Dvec, upack);
}

// round 15
// speedup vs baseline: 1.1087x; 1.0085x over previous
#include <cuda_runtime.h>
#include <cuda_fp16.h>
#include <math.h>
#include <stdint.h>

#define B_SZ 4
#define LLEN 4096
#define HDIM 1024
#define PDIM 1024
#define MROWS (B_SZ * LLEN)   /* 16384 */
#define NC 32
#define TCH (LLEN / NC)       /* 128 */

// ---------------- scratch (static device globals; no allocations) ----------
__device__ __half g_bu_re[(size_t)MROWS * PDIM];    // GEMM1 out (fp16), scan in
__device__ __half g_bu_im[(size_t)MROWS * PDIM];
__device__ __half g_u_pack [(size_t)MROWS * HDIM];  // A-fragment-packed fp16
__device__ __half g_xre_pack[(size_t)MROWS * PDIM];
__device__ __half g_xim_pack[(size_t)MROWS * PDIM];
__device__ __half g_Bre_pack[(size_t)PDIM * HDIM];  // B-fragment-packed weights
__device__ __half g_Bim_pack[(size_t)PDIM * HDIM];
__device__ __half g_Cre_pack[(size_t)HDIM * PDIM];
__device__ __half g_Cimn_pack[(size_t)HDIM * PDIM]; // NEGATED C_im
__device__ float g_carry_re[B_SZ * NC * PDIM];
__device__ float g_carry_im[B_SZ * NC * PDIM];
__device__ float g_lam_re[PDIM], g_lam_im[PDIM];
__device__ float g_lamT_re[PDIM], g_lamT_im[PDIM];
__device__ float g_gamma[PDIM];

// ====================== PTX helpers ========================================
__device__ __forceinline__ uint32_t smem_u32(const void* p) {
    uint32_t a;
    asm("{ .reg .u64 t; cvta.to.shared.u64 t, %1; cvt.u32.u64 %0, t; }"
        : "=r"(a) : "l"(p));
    return a;
}
__device__ __forceinline__ void cp16(uint32_t dst, const void* src) {
    asm volatile("cp.async.cg.shared.global [%0], [%1], 16;"
                 :: "r"(dst), "l"(src) : "memory");
}
__device__ __forceinline__ void cp_commit() {
    asm volatile("cp.async.commit_group;" ::: "memory");
}
template <int N>
__device__ __forceinline__ void cp_wait() {
    asm volatile("cp.async.wait_group %0;" :: "n"(N) : "memory");
}
__device__ __forceinline__ uint32_t h2u(__half2 h) { return *(uint32_t*)&h; }
__device__ __forceinline__ void mma_f16(float* d, const uint32_t* a, const uint32_t* b) {
    asm volatile("mma.sync.aligned.m16n8k16.row.col.f32.f16.f16.f32 "
                 "{%0,%1,%2,%3}, {%4,%5,%6,%7}, {%8,%9}, {%0,%1,%2,%3};"
                 : "+f"(d[0]), "+f"(d[1]), "+f"(d[2]), "+f"(d[3])
                 : "r"(a[0]), "r"(a[1]), "r"(a[2]), "r"(a[3]),
                   "r"(b[0]), "r"(b[1]));
}

// ====================== packed fp16 GEMM (BM128 x BN128) ===================
// MODE 0 (GEMM1): 16 chunks; z selects (B0,out0)/(B1,out1); epi *gamma; fp16 out
// MODE 1 (GEMM2): 32 chunks, >=16 -> (A1,B1); epi +Dv[n]*u (fp16 packed); fp32 out
#define ASZ 16384
#define STG_BYTES 32768
#define SMEM_TOTAL (3 * STG_BYTES)       /* 98304 -> 2 CTAs/SM */

template <int MODE>
__global__ __launch_bounds__(256, 2)
void gemm_f16p(const __half* __restrict__ A0, const __half* __restrict__ A1,
               const __half* __restrict__ B0, const __half* __restrict__ B1,
               void* __restrict__ out0, void* __restrict__ out1,
               const float* __restrict__ colscale,
               const float* __restrict__ Dv, const __half* __restrict__ Upk) {
    extern __shared__ char smemc[];
    uint32_t sb = smem_u32(smemc);
    const int tid = threadIdx.x, lane = tid & 31, wid = tid >> 5;
    const int brow = blockIdx.y * 128, bcol = blockIdx.x * 128;
    const int NCHUNK = (MODE == 0) ? 16 : 32;

    const char *Ab0, *Ab1, *Bb0, *Bb1;
    void* op;
    if (MODE == 0) {
        Ab0 = Ab1 = (const char*)A0 + (size_t)brow * 2048;
        const __half* Bsel = blockIdx.z ? B1 : B0;
        Bb0 = Bb1 = (const char*)Bsel + (size_t)bcol * 2048;
        op = blockIdx.z ? out1 : out0;
    } else {
        Ab0 = (const char*)A0 + (size_t)brow * 2048;
        Ab1 = (const char*)A1 + (size_t)brow * 2048;
        Bb0 = (const char*)B0 + (size_t)bcol * 2048;
        Bb1 = (const char*)B1 + (size_t)bcol * 2048;
        op = out0;
    }

    uint32_t agm[4], bgm[4];
#pragma unroll
    for (int j = 0; j < 4; j++) {
        int s = tid + j * 256;
        agm[j] = (uint32_t)((((s >> 7) * 64) + ((s >> 5) & 3)) * 512 + (s & 31) * 16);
        bgm[j] = (uint32_t)((((s >> 6) * 64) + ((s >> 4) & 3)) * 256 + (s & 15) * 16);
    }
    const uint32_t soff = (uint32_t)tid * 16;

    auto load_chunk = [&](int i) {
        const char* Ap = (MODE == 1 && i >= 16) ? Ab1 : Ab0;
        const char* Bp = (MODE == 1 && i >= 16) ? Bb1 : Bb0;
        uint32_t ka = (uint32_t)(i & 15) * 2048;
        uint32_t kb = (uint32_t)(i & 15) * 1024;
        uint32_t st = sb + (uint32_t)(i % 3) * STG_BYTES;
#pragma unroll
        for (int j = 0; j < 4; j++) {
            cp16(st + soff + j * 4096, Ap + agm[j] + ka);
            cp16(st + ASZ + soff + j * 4096, Bp + bgm[j] + kb);
        }
        cp_commit();
    };

    const uint32_t afr0 = (uint32_t)(((wid >> 2) * 4) * 2048 + lane * 16);
    const uint32_t bfr0 = (uint32_t)(ASZ + ((wid & 3) * 4) * 1024 + lane * 8);

    float acc[4][4][4];
#pragma unroll
    for (int f = 0; f < 4; f++)
#pragma unroll
        for (int j = 0; j < 4; j++)
#pragma unroll
            for (int c = 0; c < 4; c++) acc[f][j][c] = 0.0f;

    load_chunk(0);
    load_chunk(1);

    for (int i = 0; i < NCHUNK; i++) {
        if (i + 2 < NCHUNK) cp_wait<1>();
        else                cp_wait<0>();
        __syncthreads();
        if (i + 2 < NCHUNK) load_chunk(i + 2);
        const char* stp = smemc + (i % 3) * STG_BYTES;
#pragma unroll
        for (int kk = 0; kk < 4; kk++) {
            uint4 a[4];
            uint2 b[4];
#pragma unroll
            for (int f = 0; f < 4; f++)
                a[f] = *(const uint4*)(stp + afr0 + f * 2048 + kk * 512);
#pragma unroll
            for (int j = 0; j < 4; j++)
                b[j] = *(const uint2*)(stp + bfr0 + j * 1024 + kk * 256);
#pragma unroll
            for (int f = 0; f < 4; f++)
#pragma unroll
                for (int j = 0; j < 4; j++)
                    mma_f16(acc[f][j], &a[f].x, &b[j].x);
        }
    }

    const int lr = lane >> 2, lc = lane & 3;
    const int wm = (wid >> 2) * 64, wn = (wid & 3) * 32;
#pragma unroll
    for (int f = 0; f < 4; f++) {
        int r0 = brow + wm + f * 16 + lr;
#pragma unroll
        for (int j = 0; j < 4; j++) {
            int col = bcol + wn + j * 8 + 2 * lc;
            float d0 = acc[f][j][0], d1 = acc[f][j][1];
            float d2 = acc[f][j][2], d3 = acc[f][j][3];
            if (MODE == 0) {
                float s0 = colscale[col], s1 = colscale[col + 1];
                __half* oph = (__half*)op;
                *(uint32_t*)&oph[(size_t)r0 * 1024 + col] =
                    h2u(__floats2half2_rn(d0 * s0, d1 * s1));
                *(uint32_t*)&oph[(size_t)(r0 + 8) * 1024 + col] =
                    h2u(__floats2half2_rn(d2 * s0, d3 * s1));
            } else {
                float v0 = Dv[col], v1 = Dv[col + 1];
                size_t quad = ((size_t)(r0 >> 4) * 64 + (col >> 4)) * 32 + lane;
                uint2 uv = *(const uint2*)((const char*)Upk + quad * 16 + (j & 1) * 8);
                __half2 ulo = *(__half2*)&uv.x;
                __half2 uhi = *(__half2*)&uv.y;
                d0 += v0 * __half2float(ulo.x); d1 += v1 * __half2float(ulo.y);
                d2 += v0 * __half2float(uhi.x); d3 += v1 * __half2float(uhi.y);
                float* opf = (float*)op;
                *(float2*)&opf[(size_t)r0 * 1024 + col] = make_float2(d0, d1);
                *(float2*)&opf[(size_t)(r0 + 8) * 1024 + col] = make_float2(d2, d3);
            }
        }
    }
}

// ====================== fused prep + weight packs ==========================
__device__ __forceinline__ void pack_bw_body(
    float sm[16][260], int idx,
    const float* __restrict__ s0, __half* __restrict__ d0,
    const float* __restrict__ s1, __half* __restrict__ d1, float sgn1) {
    int z = idx >> 8, rem = idx & 255;
    int rb = rem >> 2, ks = rem & 3;
    const float* src = z ? s1 : s0;
    __half* dst = z ? d1 : d0;
    float sg = z ? sgn1 : 1.0f;
    int t = threadIdx.x;
#pragma unroll
    for (int i = 0; i < 4; i++) {
        int id = t + i * 256;
        int r = id >> 6, c = (id & 63) * 4;
        float4 v = *(const float4*)&src[(size_t)(rb * 16 + r) * 1024 + ks * 256 + c];
        sm[r][c] = sg * v.x; sm[r][c + 1] = sg * v.y;
        sm[r][c + 2] = sg * v.z; sm[r][c + 3] = sg * v.w;
    }
    __syncthreads();
#pragma unroll
    for (int i = 0; i < 4; i++) {
        int u = t + i * 256;
        int nbl = u >> 9, kbl = (u >> 5) & 15, l = u & 31;
        int g = l >> 2, tt = l & 3;
        int row = nbl * 8 + g, c = kbl * 16 + 2 * tt;
        uint2 o;
        o.x = h2u(__floats2half2_rn(sm[row][c],     sm[row][c + 1]));
        o.y = h2u(__floats2half2_rn(sm[row][c + 8], sm[row][c + 9]));
        ((uint2*)dst)[(size_t)((rb * 2 + nbl) * 64 + ks * 16 + kbl) * 32 + l] = o;
    }
}

__global__ __launch_bounds__(256)
void prep_weights(const float* __restrict__ nu_log,
                  const float* __restrict__ theta_log,
                  const float* __restrict__ gamma_log,
                  const float* __restrict__ B_re, __half* __restrict__ Bre,
                  const float* __restrict__ B_im, __half* __restrict__ Bim,
                  const float* __restrict__ C_re, __half* __restrict__ Cre,
                  const float* __restrict__ C_im, __half* __restrict__ Cimn) {
    __shared__ float sm[16][260];
    int bid = blockIdx.x;
    if (bid < 512) {
        pack_bw_body(sm, bid, B_re, Bre, B_im, Bim, 1.0f);
    } else if (bid < 1024) {
        pack_bw_body(sm, bid - 512, C_re, Cre, C_im, Cimn, -1.0f);
    } else {
        int p = (bid - 1024) * 256 + threadIdx.x;
        if (p < PDIM) {
            float mag = expf(-expf(nu_log[p]));
            float th = expf(theta_log[p]);
            float s, c; sincosf(th, &s, &c);
            float lr = mag * c, li = mag * s;
            g_lam_re[p] = lr; g_lam_im[p] = li;
            g_gamma[p] = expf(gamma_log[p]);
            float ar = lr, ai = li;
#pragma unroll
            for (int i = 0; i < 7; i++) { float nr = ar*ar - ai*ai; ai = 2.0f*ar*ai; ar = nr; }
            g_lamT_re[p] = ar; g_lamT_im[p] = ai;
        }
    }
}

// ====================== pack_Au ============================================
__global__ __launch_bounds__(256) void pack_Au(const float* __restrict__ src,
                                               __half* __restrict__ dst) {
    __shared__ float sm[16][260];
    int t = threadIdx.x, rb = blockIdx.x, ks = blockIdx.y;
#pragma unroll
    for (int i = 0; i < 4; i++) {
        int idx = t + i * 256;
        int r = idx >> 6, c = (idx & 63) * 4;
        float4 v = *(const float4*)&src[(size_t)(rb * 16 + r) * 1024 + ks * 256 + c];
        sm[r][c] = v.x; sm[r][c + 1] = v.y; sm[r][c + 2] = v.z; sm[r][c + 3] = v.w;
    }
    __syncthreads();
#pragma unroll
    for (int i = 0; i < 2; i++) {
        int q = t + i * 256;
        int kbl = q >> 5, l = q & 31, g = l >> 2, tt = l & 3;
        int c = kbl * 16 + 2 * tt;
        uint4 o;
        o.x = h2u(__floats2half2_rn(sm[g][c],         sm[g][c + 1]));
        o.y = h2u(__floats2half2_rn(sm[g + 8][c],     sm[g + 8][c + 1]));
        o.z = h2u(__floats2half2_rn(sm[g][c + 8],     sm[g][c + 9]));
        o.w = h2u(__floats2half2_rn(sm[g + 8][c + 8], sm[g + 8][c + 9]));
        ((uint4*)dst)[(size_t)(rb * 64 + ks * 16 + kbl) * 32 + l] = o;
    }
}

// ====================== scan (x2-vectorized channels) =======================
__global__ __launch_bounds__(256) void scan_pass1() {
    int pc = (blockIdx.x * 256 + threadIdx.x) * 2;
    int chunk = blockIdx.y, b = blockIdx.z;
    float lr0 = g_lam_re[pc],     li0 = g_lam_im[pc];
    float lr1 = g_lam_re[pc + 1], li1 = g_lam_im[pc + 1];
    size_t base = ((size_t)(b * LLEN + chunk * TCH)) * PDIM + pc;
    float sr0 = 0, si0 = 0, sr1 = 0, si1 = 0;
#pragma unroll 4
    for (int t = 0; t < TCH; t++) {
        __half2 hr = *(const __half2*)&g_bu_re[base + (size_t)t * PDIM];
        __half2 hi = *(const __half2*)&g_bu_im[base + (size_t)t * PDIM];
        float2 br = __half22float2(hr);
        float2 bi = __half22float2(hi);
        float n0 = fmaf(lr0, sr0, fmaf(-li0, si0, br.x));
        float m0 = fmaf(lr0, si0, fmaf( li0, sr0, bi.x));
        float n1 = fmaf(lr1, sr1, fmaf(-li1, si1, br.y));
        float m1 = fmaf(lr1, si1, fmaf( li1, sr1, bi.y));
        sr0 = n0; si0 = m0; sr1 = n1; si1 = m1;
    }
    int ci = (b * NC + chunk) * PDIM + pc;
    *(float2*)&g_carry_re[ci] = make_float2(sr0, sr1);
    *(float2*)&g_carry_im[ci] = make_float2(si0, si1);
}

__global__ void scan_pass2() {
    int gid = blockIdx.x * blockDim.x + threadIdx.x;
    if (gid >= B_SZ * PDIM) return;
    int b = gid / PDIM, p = gid % PDIM;
    float tr_ = g_lamT_re[p], ti = g_lamT_im[p];
    float cr = 0.0f, ci_ = 0.0f;
    for (int c = 0; c < NC; c++) {
        int idx = (b * NC + c) * PDIM + p;
        float sr = g_carry_re[idx], si = g_carry_im[idx];
        g_carry_re[idx] = cr; g_carry_im[idx] = ci_;
        float nr = fmaf(tr_, cr, fmaf(-ti, ci_, sr));
        float ni = fmaf(tr_, ci_, fmaf( ti, cr, si));
        cr = nr; ci_ = ni;
    }
}

// replay with carry seed; 512 channels/block; emit A-fragment-packed fp16 x
#define S3_PITCH 520
#define S3_SMEM (2 * 16 * S3_PITCH * 4)   /* 66560 B */
__global__ __launch_bounds__(256) void scan_pass3() {
    extern __shared__ float sm3[];
    float* smr = sm3;
    float* smi = sm3 + 16 * S3_PITCH;
    int pl = threadIdx.x;
    int pc = blockIdx.x * 512 + pl * 2;
    int chunk = blockIdx.y, b = blockIdx.z;
    float lr0 = g_lam_re[pc],     li0 = g_lam_im[pc];
    float lr1 = g_lam_re[pc + 1], li1 = g_lam_im[pc + 1];
    int ci = (b * NC + chunk) * PDIM + pc;
    float2 crv = *(float2*)&g_carry_re[ci];
    float2 civ = *(float2*)&g_carry_im[ci];
    float sr0 = crv.x, sr1 = crv.y, si0 = civ.x, si1 = civ.y;
    size_t base = ((size_t)(b * LLEN + chunk * TCH)) * PDIM + pc;

    for (int blk = 0; blk < TCH / 16; blk++) {
#pragma unroll 4
        for (int t = 0; t < 16; t++) {
            size_t idx = base + (size_t)(blk * 16 + t) * PDIM;
            __half2 hr = *(const __half2*)&g_bu_re[idx];
            __half2 hi = *(const __half2*)&g_bu_im[idx];
            float2 br = __half22float2(hr);
            float2 bi = __half22float2(hi);
            float n0 = fmaf(lr0, sr0, fmaf(-li0, si0, br.x));
            float m0 = fmaf(lr0, si0, fmaf( li0, sr0, bi.x));
            float n1 = fmaf(lr1, sr1, fmaf(-li1, si1, br.y));
            float m1 = fmaf(lr1, si1, fmaf( li1, sr1, bi.y));
            sr0 = n0; si0 = m0; sr1 = n1; si1 = m1;
            *(float2*)&smr[t * S3_PITCH + pl * 2] = make_float2(sr0, sr1);
            *(float2*)&smi[t * S3_PITCH + pl * 2] = make_float2(si0, si1);
        }
        __syncthreads();
        size_t rbg = (size_t)(b * LLEN + chunk * TCH + blk * 16) >> 4;
#pragma unroll
        for (int i = 0; i < 4; i++) {
            int q = pl + i * 256;                 // 0..1023
            int kbl = q >> 5, l = q & 31, g = l >> 2, tt = l & 3;
            int c = kbl * 16 + 2 * tt;
            size_t quad = (rbg * 64 + blockIdx.x * 32 + kbl) * 32 + l;
            uint4 o;
            o.x = h2u(__floats2half2_rn(smr[g * S3_PITCH + c],     smr[g * S3_PITCH + c + 1]));
            o.y = h2u(__floats2half2_rn(smr[(g + 8) * S3_PITCH + c], smr[(g + 8) * S3_PITCH + c + 1]));
            o.z = h2u(__floats2half2_rn(smr[g * S3_PITCH + c + 8], smr[g * S3_PITCH + c + 9]));
            o.w = h2u(__floats2half2_rn(smr[(g + 8) * S3_PITCH + c + 8], smr[(g + 8) * S3_PITCH + c + 9]));
            ((uint4*)g_xre_pack)[quad] = o;
            o.x = h2u(__floats2half2_rn(smi[g * S3_PITCH + c],     smi[g * S3_PITCH + c + 1]));
            o.y = h2u(__floats2half2_rn(smi[(g + 8) * S3_PITCH + c], smi[(g + 8) * S3_PITCH + c + 1]));
            o.z = h2u(__floats2half2_rn(smi[g * S3_PITCH + c + 8], smi[g * S3_PITCH + c + 9]));
            o.w = h2u(__floats2half2_rn(smi[(g + 8) * S3_PITCH + c + 8], smi[(g + 8) * S3_PITCH + c + 9]));
            ((uint4*)g_xim_pack)[quad] = o;
        }
        __syncthreads();
    }
}

// ====================== launch =============================================
extern "C" void kernel_launch(void* const* d_in, const int* in_sizes, int n_in,
                              void* d_out, int out_size) {
    const float* inputs    = (const float*)d_in[0];
    const float* nu_log    = (const float*)d_in[1];
    const float* theta_log = (const float*)d_in[2];
    const float* B_re      = (const float*)d_in[3];
    const float* B_im      = (const float*)d_in[4];
    const float* C_re      = (const float*)d_in[5];
    const float* C_im      = (const float*)d_in[6];
    const float* Dvec      = (const float*)d_in[7];
    const float* gamma_log = (const float*)d_in[8];
    float* out = (float*)d_out;

    float *gamma_p;
    __half *bu_re, *bu_im, *upack, *xre, *xim, *Bre, *Bim, *Cre, *Cimn;
    cudaGetSymbolAddress((void**)&bu_re, g_bu_re);
    cudaGetSymbolAddress((void**)&bu_im, g_bu_im);
    cudaGetSymbolAddress((void**)&gamma_p, g_gamma);
    cudaGetSymbolAddress((void**)&upack, g_u_pack);
    cudaGetSymbolAddress((void**)&xre, g_xre_pack);
    cudaGetSymbolAddress((void**)&xim, g_xim_pack);
    cudaGetSymbolAddress((void**)&Bre, g_Bre_pack);
    cudaGetSymbolAddress((void**)&Bim, g_Bim_pack);
    cudaGetSymbolAddress((void**)&Cre, g_Cre_pack);
    cudaGetSymbolAddress((void**)&Cimn, g_Cimn_pack);

    cudaFuncSetAttribute(gemm_f16p<0>, cudaFuncAttributeMaxDynamicSharedMemorySize, SMEM_TOTAL);
    cudaFuncSetAttribute(gemm_f16p<1>, cudaFuncAttributeMaxDynamicSharedMemorySize, SMEM_TOTAL);
    cudaFuncSetAttribute(scan_pass3, cudaFuncAttributeMaxDynamicSharedMemorySize, S3_SMEM);

    // launches: 0 prep_weights, 1 pack_Au, 2 GEMM1, 3 scan1(profiled),
    //           4 scan2, 5 scan3, 6 GEMM2
    prep_weights<<<1028, 256>>>(nu_log, theta_log, gamma_log,
                                B_re, Bre, B_im, Bim, C_re, Cre, C_im, Cimn);
    pack_Au<<<dim3(MROWS / 16, 4), 256>>>(inputs, upack);

    // GEMM1: Bu_{re,im}[m,p] = gamma[p] * sum_h u[m,h] * B_{re,im}[p,h]
    dim3 g1(PDIM / 128, MROWS / 128, 2);
    gemm_f16p<0><<<g1, 256, SMEM_TOTAL>>>(upack, nullptr, Bre, Bim,
                                          bu_re, bu_im, gamma_p, nullptr, nullptr);

    // chunked linear recurrence (x2-vectorized); x emitted packed fp16
    dim3 gs1(PDIM / 512, NC, B_SZ);
    scan_pass1<<<gs1, 256>>>();
    scan_pass2<<<(B_SZ * PDIM + 255) / 256, 256>>>();
    dim3 gs3(PDIM / 512, NC, B_SZ);
    scan_pass3<<<gs3, 256, S3_SMEM>>>();

    // GEMM2: out = x_re@C_re^T + x_im@(-C_im)^T + D*u (u from fp16 pack)
    dim3 g2(HDIM / 128, MROWS / 128, 1);
    gemm_f16p<1><<<g2, 256, SMEM_TOTAL>>>(xre, xim, Cre, Cimn,
                                          out, nullptr, nullptr, Dvec, upack);
}

// round 16
// speedup vs baseline: 1.1295x; 1.0187x over previous
#include <cuda_runtime.h>
#include <cuda_fp16.h>
#include <math.h>
#include <stdint.h>

#define B_SZ 4
#define LLEN 4096
#define HDIM 1024
#define PDIM 1024
#define MROWS (B_SZ * LLEN)   /* 16384 */
#define NC 64
#define TCH (LLEN / NC)       /* 64 */

// ---------------- scratch (static device globals; no allocations) ----------
__device__ __half g_bu_re[(size_t)MROWS * PDIM];    // GEMM1 out (fp16), scan in
__device__ __half g_bu_im[(size_t)MROWS * PDIM];
__device__ __half g_u_pack [(size_t)MROWS * HDIM];  // A-fragment-packed fp16
__device__ __half g_xre_pack[(size_t)MROWS * PDIM];
__device__ __half g_xim_pack[(size_t)MROWS * PDIM];
__device__ __half g_Bre_pack[(size_t)PDIM * HDIM];  // B-fragment-packed weights
__device__ __half g_Bim_pack[(size_t)PDIM * HDIM];
__device__ __half g_Cre_pack[(size_t)HDIM * PDIM];
__device__ __half g_Cimn_pack[(size_t)HDIM * PDIM]; // NEGATED C_im
__device__ float g_carry_re[B_SZ * NC * PDIM];
__device__ float g_carry_im[B_SZ * NC * PDIM];
__device__ float g_lam_re[PDIM], g_lam_im[PDIM];
__device__ float g_lamT_re[PDIM], g_lamT_im[PDIM];
__device__ float g_gamma[PDIM];

// ====================== PTX helpers ========================================
__device__ __forceinline__ uint32_t smem_u32(const void* p) {
    uint32_t a;
    asm("{ .reg .u64 t; cvta.to.shared.u64 t, %1; cvt.u32.u64 %0, t; }"
        : "=r"(a) : "l"(p));
    return a;
}
__device__ __forceinline__ void cp16(uint32_t dst, const void* src) {
    asm volatile("cp.async.cg.shared.global [%0], [%1], 16;"
                 :: "r"(dst), "l"(src) : "memory");
}
__device__ __forceinline__ void cp_commit() {
    asm volatile("cp.async.commit_group;" ::: "memory");
}
template <int N>
__device__ __forceinline__ void cp_wait() {
    asm volatile("cp.async.wait_group %0;" :: "n"(N) : "memory");
}
__device__ __forceinline__ uint32_t h2u(__half2 h) { return *(uint32_t*)&h; }
__device__ __forceinline__ void mma_f16(float* d, const uint32_t* a, const uint32_t* b) {
    asm volatile("mma.sync.aligned.m16n8k16.row.col.f32.f16.f16.f32 "
                 "{%0,%1,%2,%3}, {%4,%5,%6,%7}, {%8,%9}, {%0,%1,%2,%3};"
                 : "+f"(d[0]), "+f"(d[1]), "+f"(d[2]), "+f"(d[3])
                 : "r"(a[0]), "r"(a[1]), "r"(a[2]), "r"(a[3]),
                   "r"(b[0]), "r"(b[1]));
}

// ====================== packed fp16 GEMM (BM128 x BN128) ===================
// MODE 0 (GEMM1): 16 chunks; z selects (B0,out0)/(B1,out1); epi *gamma; fp16 out
// MODE 1 (GEMM2): 32 chunks, >=16 -> (A1,B1); epi +Dv[n]*u (fp16 packed); fp32 out
#define ASZ 16384
#define STG_BYTES 32768
#define SMEM_TOTAL (3 * STG_BYTES)       /* 98304 -> 2 CTAs/SM */

template <int MODE>
__global__ __launch_bounds__(256, 2)
void gemm_f16p(const __half* __restrict__ A0, const __half* __restrict__ A1,
               const __half* __restrict__ B0, const __half* __restrict__ B1,
               void* __restrict__ out0, void* __restrict__ out1,
               const float* __restrict__ colscale,
               const float* __restrict__ Dv, const __half* __restrict__ Upk) {
    extern __shared__ char smemc[];
    uint32_t sb = smem_u32(smemc);
    const int tid = threadIdx.x, lane = tid & 31, wid = tid >> 5;
    const int brow = blockIdx.y * 128, bcol = blockIdx.x * 128;
    const int NCHUNK = (MODE == 0) ? 16 : 32;

    const char *Ab0, *Ab1, *Bb0, *Bb1;
    void* op;
    if (MODE == 0) {
        Ab0 = Ab1 = (const char*)A0 + (size_t)brow * 2048;
        const __half* Bsel = blockIdx.z ? B1 : B0;
        Bb0 = Bb1 = (const char*)Bsel + (size_t)bcol * 2048;
        op = blockIdx.z ? out1 : out0;
    } else {
        Ab0 = (const char*)A0 + (size_t)brow * 2048;
        Ab1 = (const char*)A1 + (size_t)brow * 2048;
        Bb0 = (const char*)B0 + (size_t)bcol * 2048;
        Bb1 = (const char*)B1 + (size_t)bcol * 2048;
        op = out0;
    }

    uint32_t agm[4], bgm[4];
#pragma unroll
    for (int j = 0; j < 4; j++) {
        int s = tid + j * 256;
        agm[j] = (uint32_t)((((s >> 7) * 64) + ((s >> 5) & 3)) * 512 + (s & 31) * 16);
        bgm[j] = (uint32_t)((((s >> 6) * 64) + ((s >> 4) & 3)) * 256 + (s & 15) * 16);
    }
    const uint32_t soff = (uint32_t)tid * 16;

    auto load_chunk = [&](int i) {
        const char* Ap = (MODE == 1 && i >= 16) ? Ab1 : Ab0;
        const char* Bp = (MODE == 1 && i >= 16) ? Bb1 : Bb0;
        uint32_t ka = (uint32_t)(i & 15) * 2048;
        uint32_t kb = (uint32_t)(i & 15) * 1024;
        uint32_t st = sb + (uint32_t)(i % 3) * STG_BYTES;
#pragma unroll
        for (int j = 0; j < 4; j++) {
            cp16(st + soff + j * 4096, Ap + agm[j] + ka);
            cp16(st + ASZ + soff + j * 4096, Bp + bgm[j] + kb);
        }
        cp_commit();
    };

    const uint32_t afr0 = (uint32_t)(((wid >> 2) * 4) * 2048 + lane * 16);
    const uint32_t bfr0 = (uint32_t)(ASZ + ((wid & 3) * 4) * 1024 + lane * 8);

    float acc[4][4][4];
#pragma unroll
    for (int f = 0; f < 4; f++)
#pragma unroll
        for (int j = 0; j < 4; j++)
#pragma unroll
            for (int c = 0; c < 4; c++) acc[f][j][c] = 0.0f;

    load_chunk(0);
    load_chunk(1);

    for (int i = 0; i < NCHUNK; i++) {
        if (i + 2 < NCHUNK) cp_wait<1>();
        else                cp_wait<0>();
        __syncthreads();
        if (i + 2 < NCHUNK) load_chunk(i + 2);
        const char* stp = smemc + (i % 3) * STG_BYTES;
#pragma unroll
        for (int kk = 0; kk < 4; kk++) {
            uint4 a[4];
            uint2 b[4];
#pragma unroll
            for (int f = 0; f < 4; f++)
                a[f] = *(const uint4*)(stp + afr0 + f * 2048 + kk * 512);
#pragma unroll
            for (int j = 0; j < 4; j++)
                b[j] = *(const uint2*)(stp + bfr0 + j * 1024 + kk * 256);
#pragma unroll
            for (int f = 0; f < 4; f++)
#pragma unroll
                for (int j = 0; j < 4; j++)
                    mma_f16(acc[f][j], &a[f].x, &b[j].x);
        }
    }

    const int lr = lane >> 2, lc = lane & 3;
    const int wm = (wid >> 2) * 64, wn = (wid & 3) * 32;
#pragma unroll
    for (int f = 0; f < 4; f++) {
        int r0 = brow + wm + f * 16 + lr;
#pragma unroll
        for (int j = 0; j < 4; j++) {
            int col = bcol + wn + j * 8 + 2 * lc;
            float d0 = acc[f][j][0], d1 = acc[f][j][1];
            float d2 = acc[f][j][2], d3 = acc[f][j][3];
            if (MODE == 0) {
                float s0 = colscale[col], s1 = colscale[col + 1];
                __half* oph = (__half*)op;
                *(uint32_t*)&oph[(size_t)r0 * 1024 + col] =
                    h2u(__floats2half2_rn(d0 * s0, d1 * s1));
                *(uint32_t*)&oph[(size_t)(r0 + 8) * 1024 + col] =
                    h2u(__floats2half2_rn(d2 * s0, d3 * s1));
            } else {
                float v0 = Dv[col], v1 = Dv[col + 1];
                size_t quad = ((size_t)(r0 >> 4) * 64 + (col >> 4)) * 32 + lane;
                uint2 uv = *(const uint2*)((const char*)Upk + quad * 16 + (j & 1) * 8);
                __half2 ulo = *(__half2*)&uv.x;
                __half2 uhi = *(__half2*)&uv.y;
                d0 += v0 * __half2float(ulo.x); d1 += v1 * __half2float(ulo.y);
                d2 += v0 * __half2float(uhi.x); d3 += v1 * __half2float(uhi.y);
                float* opf = (float*)op;
                *(float2*)&opf[(size_t)r0 * 1024 + col] = make_float2(d0, d1);
                *(float2*)&opf[(size_t)(r0 + 8) * 1024 + col] = make_float2(d2, d3);
            }
        }
    }
}

// ====================== fused prep + weight packs ==========================
__device__ __forceinline__ void pack_bw_body(
    float sm[16][260], int idx,
    const float* __restrict__ s0, __half* __restrict__ d0,
    const float* __restrict__ s1, __half* __restrict__ d1, float sgn1) {
    int z = idx >> 8, rem = idx & 255;
    int rb = rem >> 2, ks = rem & 3;
    const float* src = z ? s1 : s0;
    __half* dst = z ? d1 : d0;
    float sg = z ? sgn1 : 1.0f;
    int t = threadIdx.x;
#pragma unroll
    for (int i = 0; i < 4; i++) {
        int id = t + i * 256;
        int r = id >> 6, c = (id & 63) * 4;
        float4 v = *(const float4*)&src[(size_t)(rb * 16 + r) * 1024 + ks * 256 + c];
        sm[r][c] = sg * v.x; sm[r][c + 1] = sg * v.y;
        sm[r][c + 2] = sg * v.z; sm[r][c + 3] = sg * v.w;
    }
    __syncthreads();
#pragma unroll
    for (int i = 0; i < 4; i++) {
        int u = t + i * 256;
        int nbl = u >> 9, kbl = (u >> 5) & 15, l = u & 31;
        int g = l >> 2, tt = l & 3;
        int row = nbl * 8 + g, c = kbl * 16 + 2 * tt;
        uint2 o;
        o.x = h2u(__floats2half2_rn(sm[row][c],     sm[row][c + 1]));
        o.y = h2u(__floats2half2_rn(sm[row][c + 8], sm[row][c + 9]));
        ((uint2*)dst)[(size_t)((rb * 2 + nbl) * 64 + ks * 16 + kbl) * 32 + l] = o;
    }
}

__global__ __launch_bounds__(256)
void prep_weights(const float* __restrict__ nu_log,
                  const float* __restrict__ theta_log,
                  const float* __restrict__ gamma_log,
                  const float* __restrict__ B_re, __half* __restrict__ Bre,
                  const float* __restrict__ B_im, __half* __restrict__ Bim,
                  const float* __restrict__ C_re, __half* __restrict__ Cre,
                  const float* __restrict__ C_im, __half* __restrict__ Cimn) {
    __shared__ float sm[16][260];
    int bid = blockIdx.x;
    if (bid < 512) {
        pack_bw_body(sm, bid, B_re, Bre, B_im, Bim, 1.0f);
    } else if (bid < 1024) {
        pack_bw_body(sm, bid - 512, C_re, Cre, C_im, Cimn, -1.0f);
    } else {
        int p = (bid - 1024) * 256 + threadIdx.x;
        if (p < PDIM) {
            float mag = expf(-expf(nu_log[p]));
            float th = expf(theta_log[p]);
            float s, c; sincosf(th, &s, &c);
            float lr = mag * c, li = mag * s;
            g_lam_re[p] = lr; g_lam_im[p] = li;
            g_gamma[p] = expf(gamma_log[p]);
            // Lambda^TCH, TCH = 64 = 2^6 -> 6 complex squarings
            float ar = lr, ai = li;
#pragma unroll
            for (int i = 0; i < 6; i++) { float nr = ar*ar - ai*ai; ai = 2.0f*ar*ai; ar = nr; }
            g_lamT_re[p] = ar; g_lamT_im[p] = ai;
        }
    }
}

// ====================== pack_Au ============================================
__global__ __launch_bounds__(256) void pack_Au(const float* __restrict__ src,
                                               __half* __restrict__ dst) {
    __shared__ float sm[16][260];
    int t = threadIdx.x, rb = blockIdx.x, ks = blockIdx.y;
#pragma unroll
    for (int i = 0; i < 4; i++) {
        int idx = t + i * 256;
        int r = idx >> 6, c = (idx & 63) * 4;
        float4 v = *(const float4*)&src[(size_t)(rb * 16 + r) * 1024 + ks * 256 + c];
        sm[r][c] = v.x; sm[r][c + 1] = v.y; sm[r][c + 2] = v.z; sm[r][c + 3] = v.w;
    }
    __syncthreads();
#pragma unroll
    for (int i = 0; i < 2; i++) {
        int q = t + i * 256;
        int kbl = q >> 5, l = q & 31, g = l >> 2, tt = l & 3;
        int c = kbl * 16 + 2 * tt;
        uint4 o;
        o.x = h2u(__floats2half2_rn(sm[g][c],         sm[g][c + 1]));
        o.y = h2u(__floats2half2_rn(sm[g + 8][c],     sm[g + 8][c + 1]));
        o.z = h2u(__floats2half2_rn(sm[g][c + 8],     sm[g][c + 9]));
        o.w = h2u(__floats2half2_rn(sm[g + 8][c + 8], sm[g + 8][c + 9]));
        ((uint4*)dst)[(size_t)(rb * 64 + ks * 16 + kbl) * 32 + l] = o;
    }
}

// ====================== scan (x2-vectorized, 64-step chunks) ================
__global__ __launch_bounds__(256) void scan_pass1() {
    int pc = (blockIdx.x * 256 + threadIdx.x) * 2;
    int chunk = blockIdx.y, b = blockIdx.z;
    float lr0 = g_lam_re[pc],     li0 = g_lam_im[pc];
    float lr1 = g_lam_re[pc + 1], li1 = g_lam_im[pc + 1];
    size_t base = ((size_t)(b * LLEN + chunk * TCH)) * PDIM + pc;
    float sr0 = 0, si0 = 0, sr1 = 0, si1 = 0;
#pragma unroll 4
    for (int t = 0; t < TCH; t++) {
        __half2 hr = *(const __half2*)&g_bu_re[base + (size_t)t * PDIM];
        __half2 hi = *(const __half2*)&g_bu_im[base + (size_t)t * PDIM];
        float2 br = __half22float2(hr);
        float2 bi = __half22float2(hi);
        float n0 = fmaf(lr0, sr0, fmaf(-li0, si0, br.x));
        float m0 = fmaf(lr0, si0, fmaf( li0, sr0, bi.x));
        float n1 = fmaf(lr1, sr1, fmaf(-li1, si1, br.y));
        float m1 = fmaf(lr1, si1, fmaf( li1, sr1, bi.y));
        sr0 = n0; si0 = m0; sr1 = n1; si1 = m1;
    }
    int ci = (b * NC + chunk) * PDIM + pc;
    *(float2*)&g_carry_re[ci] = make_float2(sr0, sr1);
    *(float2*)&g_carry_im[ci] = make_float2(si0, si1);
}

__global__ void scan_pass2() {
    int gid = blockIdx.x * blockDim.x + threadIdx.x;
    if (gid >= B_SZ * PDIM) return;
    int b = gid / PDIM, p = gid % PDIM;
    float tr_ = g_lamT_re[p], ti = g_lamT_im[p];
    float cr = 0.0f, ci_ = 0.0f;
    for (int c = 0; c < NC; c++) {
        int idx = (b * NC + c) * PDIM + p;
        float sr = g_carry_re[idx], si = g_carry_im[idx];
        g_carry_re[idx] = cr; g_carry_im[idx] = ci_;
        float nr = fmaf(tr_, cr, fmaf(-ti, ci_, sr));
        float ni = fmaf(tr_, ci_, fmaf( ti, cr, si));
        cr = nr; ci_ = ni;
    }
}

// replay with carry seed; 512 channels/block; emit A-fragment-packed fp16 x
#define S3_PITCH 520
#define S3_SMEM (2 * 16 * S3_PITCH * 4)   /* 66560 B */
__global__ __launch_bounds__(256) void scan_pass3() {
    extern __shared__ float sm3[];
    float* smr = sm3;
    float* smi = sm3 + 16 * S3_PITCH;
    int pl = threadIdx.x;
    int pc = blockIdx.x * 512 + pl * 2;
    int chunk = blockIdx.y, b = blockIdx.z;
    float lr0 = g_lam_re[pc],     li0 = g_lam_im[pc];
    float lr1 = g_lam_re[pc + 1], li1 = g_lam_im[pc + 1];
    int ci = (b * NC + chunk) * PDIM + pc;
    float2 crv = *(float2*)&g_carry_re[ci];
    float2 civ = *(float2*)&g_carry_im[ci];
    float sr0 = crv.x, sr1 = crv.y, si0 = civ.x, si1 = civ.y;
    size_t base = ((size_t)(b * LLEN + chunk * TCH)) * PDIM + pc;

    for (int blk = 0; blk < TCH / 16; blk++) {
#pragma unroll 4
        for (int t = 0; t < 16; t++) {
            size_t idx = base + (size_t)(blk * 16 + t) * PDIM;
            __half2 hr = *(const __half2*)&g_bu_re[idx];
            __half2 hi = *(const __half2*)&g_bu_im[idx];
            float2 br = __half22float2(hr);
            float2 bi = __half22float2(hi);
            float n0 = fmaf(lr0, sr0, fmaf(-li0, si0, br.x));
            float m0 = fmaf(lr0, si0, fmaf( li0, sr0, bi.x));
            float n1 = fmaf(lr1, sr1, fmaf(-li1, si1, br.y));
            float m1 = fmaf(lr1, si1, fmaf( li1, sr1, bi.y));
            sr0 = n0; si0 = m0; sr1 = n1; si1 = m1;
            *(float2*)&smr[t * S3_PITCH + pl * 2] = make_float2(sr0, sr1);
            *(float2*)&smi[t * S3_PITCH + pl * 2] = make_float2(si0, si1);
        }
        __syncthreads();
        size_t rbg = (size_t)(b * LLEN + chunk * TCH + blk * 16) >> 4;
#pragma unroll
        for (int i = 0; i < 4; i++) {
            int q = pl + i * 256;                 // 0..1023
            int kbl = q >> 5, l = q & 31, g = l >> 2, tt = l & 3;
            int c = kbl * 16 + 2 * tt;
            size_t quad = (rbg * 64 + blockIdx.x * 32 + kbl) * 32 + l;
            uint4 o;
            o.x = h2u(__floats2half2_rn(smr[g * S3_PITCH + c],     smr[g * S3_PITCH + c + 1]));
            o.y = h2u(__floats2half2_rn(smr[(g + 8) * S3_PITCH + c], smr[(g + 8) * S3_PITCH + c + 1]));
            o.z = h2u(__floats2half2_rn(smr[g * S3_PITCH + c + 8], smr[g * S3_PITCH + c + 9]));
            o.w = h2u(__floats2half2_rn(smr[(g + 8) * S3_PITCH + c + 8], smr[(g + 8) * S3_PITCH + c + 9]));
            ((uint4*)g_xre_pack)[quad] = o;
            o.x = h2u(__floats2half2_rn(smi[g * S3_PITCH + c],     smi[g * S3_PITCH + c + 1]));
            o.y = h2u(__floats2half2_rn(smi[(g + 8) * S3_PITCH + c], smi[(g + 8) * S3_PITCH + c + 1]));
            o.z = h2u(__floats2half2_rn(smi[g * S3_PITCH + c + 8], smi[g * S3_PITCH + c + 9]));
            o.w = h2u(__floats2half2_rn(smi[(g + 8) * S3_PITCH + c + 8], smi[(g + 8) * S3_PITCH + c + 9]));
            ((uint4*)g_xim_pack)[quad] = o;
        }
        __syncthreads();
    }
}

// ====================== launch =============================================
extern "C" void kernel_launch(void* const* d_in, const int* in_sizes, int n_in,
                              void* d_out, int out_size) {
    const float* inputs    = (const float*)d_in[0];
    const float* nu_log    = (const float*)d_in[1];
    const float* theta_log = (const float*)d_in[2];
    const float* B_re      = (const float*)d_in[3];
    const float* B_im      = (const float*)d_in[4];
    const float* C_re      = (const float*)d_in[5];
    const float* C_im      = (const float*)d_in[6];
    const float* Dvec      = (const float*)d_in[7];
    const float* gamma_log = (const float*)d_in[8];
    float* out = (float*)d_out;

    float *gamma_p;
    __half *bu_re, *bu_im, *upack, *xre, *xim, *Bre, *Bim, *Cre, *Cimn;
    cudaGetSymbolAddress((void**)&bu_re, g_bu_re);
    cudaGetSymbolAddress((void**)&bu_im, g_bu_im);
    cudaGetSymbolAddress((void**)&gamma_p, g_gamma);
    cudaGetSymbolAddress((void**)&upack, g_u_pack);
    cudaGetSymbolAddress((void**)&xre, g_xre_pack);
    cudaGetSymbolAddress((void**)&xim, g_xim_pack);
    cudaGetSymbolAddress((void**)&Bre, g_Bre_pack);
    cudaGetSymbolAddress((void**)&Bim, g_Bim_pack);
    cudaGetSymbolAddress((void**)&Cre, g_Cre_pack);
    cudaGetSymbolAddress((void**)&Cimn, g_Cimn_pack);

    cudaFuncSetAttribute(gemm_f16p<0>, cudaFuncAttributeMaxDynamicSharedMemorySize, SMEM_TOTAL);
    cudaFuncSetAttribute(gemm_f16p<1>, cudaFuncAttributeMaxDynamicSharedMemorySize, SMEM_TOTAL);
    cudaFuncSetAttribute(scan_pass3, cudaFuncAttributeMaxDynamicSharedMemorySize, S3_SMEM);

    // launches: 0 prep_weights, 1 pack_Au, 2 GEMM1, 3 scan1(profiled),
    //           4 scan2, 5 scan3, 6 GEMM2
    prep_weights<<<1028, 256>>>(nu_log, theta_log, gamma_log,
                                B_re, Bre, B_im, Bim, C_re, Cre, C_im, Cimn);
    pack_Au<<<dim3(MROWS / 16, 4), 256>>>(inputs, upack);

    // GEMM1: Bu_{re,im}[m,p] = gamma[p] * sum_h u[m,h] * B_{re,im}[p,h]
    dim3 g1(PDIM / 128, MROWS / 128, 2);
    gemm_f16p<0><<<g1, 256, SMEM_TOTAL>>>(upack, nullptr, Bre, Bim,
                                          bu_re, bu_im, gamma_p, nullptr, nullptr);

    // chunked linear recurrence (x2-vectorized, 64 chunks); x packed fp16
    dim3 gs1(PDIM / 512, NC, B_SZ);
    scan_pass1<<<gs1, 256>>>();
    scan_pass2<<<(B_SZ * PDIM + 255) / 256, 256>>>();
    dim3 gs3(PDIM / 512, NC, B_SZ);
    scan_pass3<<<gs3, 256, S3_SMEM>>>();

    // GEMM2: out = x_re@C_re^T + x_im@(-C_im)^T + D*u (u from fp16 pack)
    dim3 g2(HDIM / 128, MROWS / 128, 1);
    gemm_f16p<1><<<g2, 256, SMEM_TOTAL>>>(xre, xim, Cre, Cimn,
                                          out, nullptr, nullptr, Dvec, upack);
}